// round 11
// baseline (speedup 1.0000x reference)
#include <cuda_runtime.h>
#include <cuda_bf16.h>
#include <math.h>
#include <cstdint>

#define B_ 16
#define T_ 512
#define IDIM_ 320
#define CD_ 1024
#define GD_ 4096   // 4*CD
#define HD_ 1024
#define LAYERS_ 4
#define NBLK_ 128  // persistent grid: <= 148 SMs -> all co-resident

typedef unsigned long long ull;
typedef unsigned int uint;

// ---------------- scratch (static device globals; no runtime alloc) ----------------
__device__ float g_xg[(size_t)B_ * T_ * GD_];        // precomputed input gates
__device__ float g_x [(size_t)B_ * T_ * CD_];        // layer io buffer (ys)
__device__ float g_hT[CD_ * B_];                     // h transposed: hT[cell][b]
__device__ ull   g_bar;                              // ticket barrier (monotonic)
__device__ __align__(16) __nv_bfloat16 g_ah[(size_t)B_ * T_ * CD_]; // A hi
__device__ __align__(16) __nv_bfloat16 g_al[(size_t)B_ * T_ * CD_]; // A lo
__device__ __align__(16) __nv_bfloat16 g_bh[(size_t)GD_ * CD_];     // B hi
__device__ __align__(16) __nv_bfloat16 g_bl[(size_t)GD_ * CD_];     // B lo

// ---------------- packed fp32x2 helpers (step kernel) ----------------
__device__ __forceinline__ ull fma2(ull a, ull b, ull c) {
    ull d;
    asm("fma.rn.f32x2 %0, %1, %2, %3;" : "=l"(d) : "l"(a), "l"(b), "l"(c));
    return d;
}
__device__ __forceinline__ ull add2(ull a, ull b) {
    ull d;
    asm("add.rn.f32x2 %0, %1, %2;" : "=l"(d) : "l"(a), "l"(b));
    return d;
}
__device__ __forceinline__ ull pack2(float x, float y) {
    ull d;
    asm("mov.b64 %0, {%1, %2};" : "=l"(d) : "f"(x), "f"(y));
    return d;
}
__device__ __forceinline__ float2 unpack2(ull v) {
    float2 r;
    asm("mov.b64 {%0, %1}, %2;" : "=f"(r.x), "=f"(r.y) : "l"(v));
    return r;
}
__device__ __forceinline__ float sigf(float x) { return 1.f / (1.f + expf(-x)); }

#define HSTRIDE 20   // padded row stride (floats) for transposed h in smem

// ---------------- bf16 split conversion ----------------
// hi = bf16(x); lo = bf16(x - hi). Optional mask: zero rows with t >= ilens[b].
__global__ void __launch_bounds__(256) conv_split_kernel(
    const float* __restrict__ x, __nv_bfloat16* __restrict__ hi,
    __nv_bfloat16* __restrict__ lo, int n, int K, const int* __restrict__ ilens)
{
    int i = (blockIdx.x * 256 + threadIdx.x) * 2;
    if (i >= n) return;
    float2 v = *(const float2*)(x + i);
    if (ilens) {
        int m = i / K;
        int t = m & (T_ - 1);
        int b = m >> 9;
        if (t >= ilens[b]) { v.x = 0.f; v.y = 0.f; }
    }
    __nv_bfloat162 h2, l2;
    h2.x = __float2bfloat16_rn(v.x);
    h2.y = __float2bfloat16_rn(v.y);
    l2.x = __float2bfloat16_rn(v.x - __bfloat162float(h2.x));
    l2.y = __float2bfloat16_rn(v.y - __bfloat162float(h2.y));
    *(__nv_bfloat162*)(hi + i) = h2;
    *(__nv_bfloat162*)(lo + i) = l2;
}

// ---------------- MMA helpers ----------------
__device__ __forceinline__ void ldmx4(uint& r0, uint& r1, uint& r2, uint& r3,
                                      const __nv_bfloat16* p) {
    uint a = (uint)__cvta_generic_to_shared(p);
    asm volatile("ldmatrix.sync.aligned.m8n8.x4.shared.b16 {%0,%1,%2,%3}, [%4];"
                 : "=r"(r0), "=r"(r1), "=r"(r2), "=r"(r3) : "r"(a));
}
__device__ __forceinline__ void mma16816(float* d, const uint* a, uint b0, uint b1) {
    asm volatile(
        "mma.sync.aligned.m16n8k16.row.col.f32.bf16.bf16.f32 "
        "{%0,%1,%2,%3}, {%4,%5,%6,%7}, {%8,%9}, {%0,%1,%2,%3};"
        : "+f"(d[0]), "+f"(d[1]), "+f"(d[2]), "+f"(d[3])
        : "r"(a[0]), "r"(a[1]), "r"(a[2]), "r"(a[3]), "r"(b0), "r"(b1));
}

// ---------------- bf16x3 GEMM (NT): C = A*B^T + bias, fp32 accum ----------------
// R5-validated structure (pipe-capped): 128x128x32 tiles, 256 threads, 8 warps
// (4M x 2N, warp 32x64), register-prefetch ping-pong smem, ONE sync per slab.
// Virtual K'' = 3K over segments (Ah,Bh),(Al,Bh),(Ah,Bl).
// Dead tiles (t0 >= ilens[b]): TANH=0 return; TANH=1 skip mainloop -> tanh(bias).
#define SPAD 40  // bf16 row stride (32 + 8 pad): conflict-free ldmatrix phases
template <int TANH>
__global__ void __launch_bounds__(256) gemm_bf16x3_kernel(
    const __nv_bfloat16* __restrict__ Ah, const __nv_bfloat16* __restrict__ Al,
    const __nv_bfloat16* __restrict__ Bh, const __nv_bfloat16* __restrict__ Bl,
    const float* __restrict__ b1, const float* __restrict__ b2,
    float* __restrict__ C, int M, int N, int K, const int* __restrict__ ilens)
{
    __shared__ __align__(16) __nv_bfloat16 As[2][128][SPAD];
    __shared__ __align__(16) __nv_bfloat16 Bs[2][128][SPAD];

    const int tid  = threadIdx.x;
    const int m0   = blockIdx.y * 128;
    const int n0   = blockIdx.x * 128;
    const int srow = tid >> 1;           // staging: row 0..127
    const int scol = (tid & 1) * 16;     // staging: k offset 0 or 16
    const int lane = tid & 31;
    const int warp = tid >> 5;
    const int wm   = warp & 3;           // 4 warps along M (32 rows each)
    const int wn   = warp >> 2;          // 2 warps along N (64 cols each)

    const bool tdead = ((m0 & 511) >= __ldg(ilens + (m0 >> 9)));
    if (!TANH && tdead) return;

    const int perseg = K >> 5;           // slabs per segment
    const int nslab  = 3 * perseg;

    float acc[2][8][4];
#pragma unroll
    for (int i = 0; i < 2; ++i)
#pragma unroll
        for (int j = 0; j < 8; ++j)
#pragma unroll
            for (int q = 0; q < 4; ++q) acc[i][j][q] = 0.f;

    if (!tdead) {
        auto srcA = [&](int s) -> const uint4* {
            int seg = s / perseg, kin = (s - seg * perseg) * 32;
            const __nv_bfloat16* A = (seg == 1) ? Al : Ah;
            return (const uint4*)(A + (size_t)(m0 + srow) * K + kin + scol);
        };
        auto srcB = [&](int s) -> const uint4* {
            int seg = s / perseg, kin = (s - seg * perseg) * 32;
            const __nv_bfloat16* Bp = (seg == 2) ? Bl : Bh;
            return (const uint4*)(Bp + (size_t)(n0 + srow) * K + kin + scol);
        };

        // prologue: slab 0 -> buffer 0
        {
            const uint4* pa = srcA(0);
            const uint4* pb = srcB(0);
            uint4 a0 = pa[0], a1 = pa[1], bq0 = pb[0], bq1 = pb[1];
            *(uint4*)&As[0][srow][scol]     = a0;
            *(uint4*)&As[0][srow][scol + 8] = a1;
            *(uint4*)&Bs[0][srow][scol]     = bq0;
            *(uint4*)&Bs[0][srow][scol + 8] = bq1;
        }
        __syncthreads();

        for (int s = 0; s < nslab; ++s) {
            const int buf = s & 1;
            const bool has = (s + 1) < nslab;
            uint4 na0, na1, nb0, nb1;
            if (has) {
                const uint4* pa = srcA(s + 1);
                const uint4* pb = srcB(s + 1);
                na0 = pa[0]; na1 = pa[1]; nb0 = pb[0]; nb1 = pb[1];
            }

#pragma unroll
            for (int kh = 0; kh < 2; ++kh) {
                const int rq = lane & 15;
                const int cq = kh * 16 + ((lane >> 4) << 3);
                uint af[2][4];
#pragma unroll
                for (int mi = 0; mi < 2; ++mi)
                    ldmx4(af[mi][0], af[mi][1], af[mi][2], af[mi][3],
                          &As[buf][wm * 32 + mi * 16 + rq][cq]);
                uint bf4[4][4];
#pragma unroll
                for (int nq = 0; nq < 4; ++nq)
                    ldmx4(bf4[nq][0], bf4[nq][1], bf4[nq][2], bf4[nq][3],
                          &Bs[buf][wn * 64 + nq * 16 + rq][cq]);
#pragma unroll
                for (int mi = 0; mi < 2; ++mi)
#pragma unroll
                    for (int nq = 0; nq < 4; ++nq) {
                        mma16816(acc[mi][2 * nq],     af[mi], bf4[nq][0], bf4[nq][2]);
                        mma16816(acc[mi][2 * nq + 1], af[mi], bf4[nq][1], bf4[nq][3]);
                    }
            }

            if (has) {
                const int nb = buf ^ 1;
                *(uint4*)&As[nb][srow][scol]     = na0;
                *(uint4*)&As[nb][srow][scol + 8] = na1;
                *(uint4*)&Bs[nb][srow][scol]     = nb0;
                *(uint4*)&Bs[nb][srow][scol + 8] = nb1;
                __syncthreads();
            }
        }
    }

    // epilogue: lane l holds c[r + {0,8}][c + {0,1}], r = l>>2, c = 2*(l&3)
    // (masked/dead rows have acc = 0 -> TANH path yields tanh(bias) naturally)
    const int r  = lane >> 2;
    const int cq = (lane & 3) * 2;
#pragma unroll
    for (int mi = 0; mi < 2; ++mi) {
#pragma unroll
        for (int nj = 0; nj < 8; ++nj) {
            const int m1 = m0 + wm * 32 + mi * 16 + r;
            const int n1 = n0 + wn * 64 + nj * 8 + cq;
            float bb0 = b1 ? __ldg(b1 + n1) : 0.f;
            float bb1 = b1 ? __ldg(b1 + n1 + 1) : 0.f;
            if (b2) { bb0 += __ldg(b2 + n1); bb1 += __ldg(b2 + n1 + 1); }
            float v0 = acc[mi][nj][0] + bb0;
            float v1 = acc[mi][nj][1] + bb1;
            float v2 = acc[mi][nj][2] + bb0;
            float v3 = acc[mi][nj][3] + bb1;
            if (TANH) { v0 = tanhf(v0); v1 = tanhf(v1); v2 = tanhf(v2); v3 = tanhf(v3); }
            *(float2*)(C + (size_t)m1 * N + n1)       = make_float2(v0, v1);
            *(float2*)(C + (size_t)(m1 + 8) * N + n1) = make_float2(v2, v3);
        }
    }
}

// ---------------- persistent LSTM layer kernel (512 threads, k-split warps) ----------------
// Vectorized W loads (LDG.128 per gate row per j) + batch-quad truncation.
// lane owns k = koff + j*128 + lane*4 (+kc); acc layout identical to R10
// (acc[p*4+g], p = batch pair), so reduction/gather below is unchanged.
#define FMA_NEST(QN)                                                          \
    _Pragma("unroll 1")                                                       \
    for (int j = 0; j < 4; ++j) {                                             \
        const int kb = koff + j * 128 + lane * 4;                             \
        const float4 wq0 = *(const float4*)(w0p + kb);                        \
        const float4 wq1 = *(const float4*)(w1p + kb);                        \
        const float4 wq2 = *(const float4*)(w2p + kb);                        \
        const float4 wq3 = *(const float4*)(w3p + kb);                        \
        const float w0a[4] = {wq0.x, wq0.y, wq0.z, wq0.w};                    \
        const float w1a[4] = {wq1.x, wq1.y, wq1.z, wq1.w};                    \
        const float w2a[4] = {wq2.x, wq2.y, wq2.z, wq2.w};                    \
        const float w3a[4] = {wq3.x, wq3.y, wq3.z, wq3.w};                    \
        _Pragma("unroll")                                                     \
        for (int kc = 0; kc < 4; ++kc) {                                      \
            const ull wp0 = pack2(w0a[kc], w0a[kc]);                          \
            const ull wp1 = pack2(w1a[kc], w1a[kc]);                          \
            const ull wp2 = pack2(w2a[kc], w2a[kc]);                          \
            const ull wp3 = pack2(w3a[kc], w3a[kc]);                          \
            const float* hrow = hs + (kb + kc) * HSTRIDE;                     \
            _Pragma("unroll")                                                 \
            for (int bq = 0; bq < (QN); ++bq) {                               \
                const ulonglong2 h2 = *(const ulonglong2*)(hrow + bq * 4);    \
                const int i0 = (2 * bq) * 4;                                  \
                const int i1 = (2 * bq + 1) * 4;                              \
                acc[i0+0] = fma2(wp0, h2.x, acc[i0+0]);                       \
                acc[i0+1] = fma2(wp1, h2.x, acc[i0+1]);                       \
                acc[i0+2] = fma2(wp2, h2.x, acc[i0+2]);                       \
                acc[i0+3] = fma2(wp3, h2.x, acc[i0+3]);                       \
                acc[i1+0] = fma2(wp0, h2.y, acc[i1+0]);                       \
                acc[i1+1] = fma2(wp1, h2.y, acc[i1+1]);                       \
                acc[i1+2] = fma2(wp2, h2.y, acc[i1+2]);                       \
                acc[i1+3] = fma2(wp3, h2.y, acc[i1+3]);                       \
            }                                                                 \
        }                                                                     \
    }

__global__ void __launch_bounds__(512) lstm_layer_kernel(
    const float* __restrict__ Whh,   // [4096,1024]
    const float* __restrict__ xg,    // [B*T,4096]
    float* __restrict__ ys,          // [B*T,1024]
    float* __restrict__ hT,          // [1024,16]
    const int* __restrict__ ilens)
{
    extern __shared__ float hs[];                    // [1024][HSTRIDE]
    ull* comb = (ull*)(hs + CD_ * HSTRIDE);          // [8*32] flat
    const int tid  = threadIdx.x;
    const int lane = tid & 31;
    const int warp = tid >> 5;                       // 0..15
    const int wc   = warp & 7;
    const int kh   = warp >> 3;
    const int cell = blockIdx.x * 8 + wc;
    const ull  G   = (ull)gridDim.x;

    const int koff = kh * 512;
    const float* w0p = Whh + (size_t)(0 * CD_ + cell) * CD_;
    const float* w1p = Whh + (size_t)(1 * CD_ + cell) * CD_;
    const float* w2p = Whh + (size_t)(2 * CD_ + cell) * CD_;
    const float* w3p = Whh + (size_t)(3 * CD_ + cell) * CD_;

    const int il_reg = (lane < B_) ? __ldg(ilens + lane) : 0;
    float creg = 0.f;

    for (int t = 0; t < T_; ++t) {
        const uint bal  = __ballot_sync(0xffffffffu, t < il_reg);
        const int  live = __popc(bal);               // live batches (>=1)
        const bool alive = (kh == 0) && (lane < B_) && (t < il_reg);

        float xgi = 0.f, xgf = 0.f, xgg = 0.f, xgo = 0.f;
        size_t orow = 0;
        if (alive) {
            orow = (size_t)(lane * T_ + t);
            const float* xr = xg + orow * GD_ + cell;
            xgi = __ldg(xr);
            xgf = __ldg(xr + CD_);
            xgg = __ldg(xr + 2 * CD_);
            xgo = __ldg(xr + 3 * CD_);
        }

        ull acc[32];
#pragma unroll
        for (int i = 0; i < 32; ++i) acc[i] = 0ULL;

        if (t > 0) {
            const int qn = (live > 8) ? 4 : ((live > 4) ? 2 : 1);  // staged quads
            const float4* src = (const float4*)hT;
#pragma unroll 4
            for (int i = tid; i < CD_ * B_ / 4; i += 512) {
                if ((i & 3) < qn) {
                    float4 v = __ldcg(src + i);
                    const int k  = i >> 2;
                    const int bq = (i & 3) * 4;
                    float* d = hs + k * HSTRIDE + bq;
                    d[0] = v.x; d[1] = v.y; d[2] = v.z; d[3] = v.w;
                }
            }
            __syncthreads();

            if (live > 8)      { FMA_NEST(4) }
            else if (live > 4) { FMA_NEST(2) }
            else               { FMA_NEST(1) }
        }

#pragma unroll
        for (int s = 0; s < 5; ++s) {
            const int off = 16 >> s;
            const int n   = 16 >> s;
            const bool hi = (lane & off) != 0;
#pragma unroll
            for (int i = 0; i < n; ++i) {
                ull send = hi ? acc[i] : acc[i + n];
                ull r = __shfl_xor_sync(0xffffffffu, send, off);
                acc[i] = add2(hi ? acc[i + n] : acc[i], r);
            }
        }

        if (kh == 1) comb[wc * 32 + lane] = acc[0];
        __syncthreads();
        ull tot = acc[0];
        if (kh == 0) tot = add2(tot, comb[wc * 32 + lane]);

        const int srcl = (lane >> 1) * 4;
        const ull r0 = __shfl_sync(0xffffffffu, tot, srcl + 0);
        const ull r1 = __shfl_sync(0xffffffffu, tot, srcl + 1);
        const ull r2 = __shfl_sync(0xffffffffu, tot, srcl + 2);
        const ull r3 = __shfl_sync(0xffffffffu, tot, srcl + 3);

        if (alive) {
            const bool oddb = (lane & 1) != 0;
            const float2 p0 = unpack2(r0), p1 = unpack2(r1), p2 = unpack2(r2), p3 = unpack2(r3);
            const float gi = (oddb ? p0.y : p0.x) + xgi;
            const float gf = (oddb ? p1.y : p1.x) + xgf;
            const float gg = (oddb ? p2.y : p2.x) + xgg;
            const float go = (oddb ? p3.y : p3.x) + xgo;
            const float cn = sigf(gf) * creg + sigf(gi) * tanhf(gg);
            creg = cn;
            const float hn = sigf(go) * tanhf(cn);
            ys[orow * CD_ + cell] = hn;
            hT[cell * B_ + lane]  = hn;
        }

        // grid-wide ticket barrier (monotonic, replay-safe)
        __threadfence();
        __syncthreads();
        if (tid == 0) {
            ull x = atomicAdd(&g_bar, 1ULL);
            ull target = x - (x % G) + G;
            while (*(volatile ull*)&g_bar < target) { }
        }
        __syncthreads();
    }
}

// ---------------- ilens tail ----------------
__global__ void write_tail_kernel(float* __restrict__ out, const int* __restrict__ ilens,
                                  long long base, long long out_size) {
    int i = threadIdx.x;
    if (i < B_ && base + i < out_size) out[base + i] = (float)ilens[i];
}

// ---------------- launch ----------------
extern "C" void kernel_launch(void* const* d_in, const int* in_sizes, int n_in,
                              void* d_out, int out_size)
{
    const float* xpad  = (const float*)d_in[0];   // [B,T,IDIM]
    const float* Wih0  = (const float*)d_in[1];   // [4096,320]
    const float* WihR  = (const float*)d_in[2];   // [3,4096,1024]
    const float* Whh   = (const float*)d_in[3];   // [4,4096,1024]
    const float* bih   = (const float*)d_in[4];   // [4,4096]
    const float* bhh   = (const float*)d_in[5];   // [4,4096]
    const float* Wlast = (const float*)d_in[6];   // [1024,1024]
    const float* blast = (const float*)d_in[7];   // [1024]
    const int*   ilens = (const int*)d_in[8];     // [16]
    float* out = (float*)d_out;

    float *xg, *xb, *hT;
    __nv_bfloat16 *ah, *al, *bh, *bl;
    cudaGetSymbolAddress((void**)&xg, g_xg);
    cudaGetSymbolAddress((void**)&xb, g_x);
    cudaGetSymbolAddress((void**)&hT, g_hT);
    cudaGetSymbolAddress((void**)&ah, g_ah);
    cudaGetSymbolAddress((void**)&al, g_al);
    cudaGetSymbolAddress((void**)&bh, g_bh);
    cudaGetSymbolAddress((void**)&bl, g_bl);

    const int smem_step = CD_ * HSTRIDE * 4 + 8 * 32 * 8;  // 81920 + 2048
    cudaFuncSetAttribute(lstm_layer_kernel,
                         cudaFuncAttributeMaxDynamicSharedMemorySize, smem_step);

    const int M = B_ * T_;  // 8192

    for (int l = 0; l < LAYERS_; ++l) {
        const float* Ain = (l == 0) ? xpad : xb;
        const float* Bw  = (l == 0) ? Wih0 : (WihR + (size_t)(l - 1) * GD_ * CD_);
        const int K = (l == 0) ? IDIM_ : CD_;

        {
            int nA = M * K;
            conv_split_kernel<<<(nA / 2 + 255) / 256, 256>>>(Ain, ah, al, nA, K, nullptr);
            int nB = GD_ * K;
            conv_split_kernel<<<(nB / 2 + 255) / 256, 256>>>(Bw, bh, bl, nB, K, nullptr);
        }

        dim3 grid_xg(GD_ / 128, M / 128);
        gemm_bf16x3_kernel<0><<<grid_xg, 256>>>(ah, al, bh, bl,
                                                bih + l * GD_, bhh + l * GD_,
                                                xg, M, GD_, K, ilens);

        const float* Wl = Whh + (size_t)l * GD_ * CD_;
        lstm_layer_kernel<<<NBLK_, 512, smem_step>>>(Wl, xg, xb, hT, ilens);
    }

    // projection: conv masks dead rows (acc=0 -> tanh(bias)); dead tiles skip mainloop
    {
        int nA = M * CD_;
        conv_split_kernel<<<(nA / 2 + 255) / 256, 256>>>(xb, ah, al, nA, CD_, ilens);
        int nB = HD_ * CD_;
        conv_split_kernel<<<(nB / 2 + 255) / 256, 256>>>(Wlast, bh, bl, nB, CD_, nullptr);
        dim3 grid_p(HD_ / 128, M / 128);
        gemm_bf16x3_kernel<1><<<grid_p, 256>>>(ah, al, bh, bl, blast, nullptr,
                                               out, M, HD_, CD_, ilens);
    }

    const long long base = (long long)B_ * T_ * HD_;  // 8388608
    if ((long long)out_size > base)
        write_tail_kernel<<<1, 32>>>(out, ilens, base, (long long)out_size);
}

// round 14
// speedup vs baseline: 1.1360x; 1.1360x over previous
#include <cuda_runtime.h>
#include <cuda_bf16.h>
#include <math.h>
#include <cstdint>

#define B_ 16
#define T_ 512
#define IDIM_ 320
#define CD_ 1024
#define GD_ 4096   // 4*CD
#define HD_ 1024
#define LAYERS_ 4
#define NBLK_ 128  // persistent grid: <= 148 SMs -> all co-resident

typedef unsigned long long ull;
typedef unsigned int uint;

// ---------------- scratch (static device globals; no runtime alloc) ----------------
__device__ float g_xg[(size_t)B_ * T_ * GD_];        // precomputed input gates
__device__ float g_x [(size_t)B_ * T_ * CD_];        // layer io buffer (ys)
__device__ float g_hT[CD_ * B_];                     // h transposed: hT[cell][b]
__device__ ull   g_cnt8[8 * 32];                     // sharded ticket counters (256B apart)
__device__ __align__(16) __nv_bfloat16 g_ah[(size_t)B_ * T_ * CD_]; // A hi
__device__ __align__(16) __nv_bfloat16 g_al[(size_t)B_ * T_ * CD_]; // A lo
__device__ __align__(16) __nv_bfloat16 g_bh[(size_t)GD_ * CD_];     // B hi
__device__ __align__(16) __nv_bfloat16 g_bl[(size_t)GD_ * CD_];     // B lo

// ---------------- packed fp32x2 helpers (step kernel) ----------------
__device__ __forceinline__ ull fma2(ull a, ull b, ull c) {
    ull d;
    asm("fma.rn.f32x2 %0, %1, %2, %3;" : "=l"(d) : "l"(a), "l"(b), "l"(c));
    return d;
}
__device__ __forceinline__ ull add2(ull a, ull b) {
    ull d;
    asm("add.rn.f32x2 %0, %1, %2;" : "=l"(d) : "l"(a), "l"(b));
    return d;
}
__device__ __forceinline__ ull pack2(float x, float y) {
    ull d;
    asm("mov.b64 %0, {%1, %2};" : "=l"(d) : "f"(x), "f"(y));
    return d;
}
__device__ __forceinline__ float2 unpack2(ull v) {
    float2 r;
    asm("mov.b64 {%0, %1}, %2;" : "=f"(r.x), "=f"(r.y) : "l"(v));
    return r;
}
__device__ __forceinline__ float sigf(float x) { return 1.f / (1.f + expf(-x)); }

#define HSTRIDE 20   // padded row stride (floats) for transposed h in smem

// ---------------- bf16 split conversion ----------------
// hi = bf16(x); lo = bf16(x - hi). Optional mask: zero rows with t >= ilens[b].
__global__ void __launch_bounds__(256) conv_split_kernel(
    const float* __restrict__ x, __nv_bfloat16* __restrict__ hi,
    __nv_bfloat16* __restrict__ lo, int n, int K, const int* __restrict__ ilens)
{
    int i = (blockIdx.x * 256 + threadIdx.x) * 2;
    if (i >= n) return;
    float2 v = *(const float2*)(x + i);
    if (ilens) {
        int m = i / K;
        int t = m & (T_ - 1);
        int b = m >> 9;
        if (t >= ilens[b]) { v.x = 0.f; v.y = 0.f; }
    }
    __nv_bfloat162 h2, l2;
    h2.x = __float2bfloat16_rn(v.x);
    h2.y = __float2bfloat16_rn(v.y);
    l2.x = __float2bfloat16_rn(v.x - __bfloat162float(h2.x));
    l2.y = __float2bfloat16_rn(v.y - __bfloat162float(h2.y));
    *(__nv_bfloat162*)(hi + i) = h2;
    *(__nv_bfloat162*)(lo + i) = l2;
}

// ---------------- MMA helpers ----------------
__device__ __forceinline__ void ldmx4(uint& r0, uint& r1, uint& r2, uint& r3,
                                      const __nv_bfloat16* p) {
    uint a = (uint)__cvta_generic_to_shared(p);
    asm volatile("ldmatrix.sync.aligned.m8n8.x4.shared.b16 {%0,%1,%2,%3}, [%4];"
                 : "=r"(r0), "=r"(r1), "=r"(r2), "=r"(r3) : "r"(a));
}
__device__ __forceinline__ void mma16816(float* d, const uint* a, uint b0, uint b1) {
    asm volatile(
        "mma.sync.aligned.m16n8k16.row.col.f32.bf16.bf16.f32 "
        "{%0,%1,%2,%3}, {%4,%5,%6,%7}, {%8,%9}, {%0,%1,%2,%3};"
        : "+f"(d[0]), "+f"(d[1]), "+f"(d[2]), "+f"(d[3])
        : "r"(a[0]), "r"(a[1]), "r"(a[2]), "r"(a[3]), "r"(b0), "r"(b1));
}

// ---------------- bf16x3 GEMM (NT): C = A*B^T + bias, fp32 accum ----------------
// R5-validated structure: 128x128x32 tiles, 256 threads, 8 warps (4M x 2N,
// warp 32x64), register-prefetch ping-pong smem, ONE sync per slab.
// Virtual K'' = 3K over segments (Ah,Bh),(Al,Bh),(Ah,Bl).
// Dead tiles (t0 >= ilens[b]): TANH=0 return; TANH=1 skip mainloop -> tanh(bias).
#define SPAD 40  // bf16 row stride (32 + 8 pad): conflict-free ldmatrix phases
template <int TANH>
__global__ void __launch_bounds__(256) gemm_bf16x3_kernel(
    const __nv_bfloat16* __restrict__ Ah, const __nv_bfloat16* __restrict__ Al,
    const __nv_bfloat16* __restrict__ Bh, const __nv_bfloat16* __restrict__ Bl,
    const float* __restrict__ b1, const float* __restrict__ b2,
    float* __restrict__ C, int M, int N, int K, const int* __restrict__ ilens)
{
    __shared__ __align__(16) __nv_bfloat16 As[2][128][SPAD];
    __shared__ __align__(16) __nv_bfloat16 Bs[2][128][SPAD];

    const int tid  = threadIdx.x;
    const int m0   = blockIdx.y * 128;
    const int n0   = blockIdx.x * 128;
    const int srow = tid >> 1;           // staging: row 0..127
    const int scol = (tid & 1) * 16;     // staging: k offset 0 or 16
    const int lane = tid & 31;
    const int warp = tid >> 5;
    const int wm   = warp & 3;           // 4 warps along M (32 rows each)
    const int wn   = warp >> 2;          // 2 warps along N (64 cols each)

    const bool tdead = ((m0 & 511) >= __ldg(ilens + (m0 >> 9)));
    if (!TANH && tdead) return;

    const int perseg = K >> 5;           // slabs per segment
    const int nslab  = 3 * perseg;

    float acc[2][8][4];
#pragma unroll
    for (int i = 0; i < 2; ++i)
#pragma unroll
        for (int j = 0; j < 8; ++j)
#pragma unroll
            for (int q = 0; q < 4; ++q) acc[i][j][q] = 0.f;

    if (!tdead) {
        auto srcA = [&](int s) -> const uint4* {
            int seg = s / perseg, kin = (s - seg * perseg) * 32;
            const __nv_bfloat16* A = (seg == 1) ? Al : Ah;
            return (const uint4*)(A + (size_t)(m0 + srow) * K + kin + scol);
        };
        auto srcB = [&](int s) -> const uint4* {
            int seg = s / perseg, kin = (s - seg * perseg) * 32;
            const __nv_bfloat16* Bp = (seg == 2) ? Bl : Bh;
            return (const uint4*)(Bp + (size_t)(n0 + srow) * K + kin + scol);
        };

        // prologue: slab 0 -> buffer 0
        {
            const uint4* pa = srcA(0);
            const uint4* pb = srcB(0);
            uint4 a0 = pa[0], a1 = pa[1], bq0 = pb[0], bq1 = pb[1];
            *(uint4*)&As[0][srow][scol]     = a0;
            *(uint4*)&As[0][srow][scol + 8] = a1;
            *(uint4*)&Bs[0][srow][scol]     = bq0;
            *(uint4*)&Bs[0][srow][scol + 8] = bq1;
        }
        __syncthreads();

        for (int s = 0; s < nslab; ++s) {
            const int buf = s & 1;
            const bool has = (s + 1) < nslab;
            uint4 na0, na1, nb0, nb1;
            if (has) {
                const uint4* pa = srcA(s + 1);
                const uint4* pb = srcB(s + 1);
                na0 = pa[0]; na1 = pa[1]; nb0 = pb[0]; nb1 = pb[1];
            }

#pragma unroll
            for (int kh = 0; kh < 2; ++kh) {
                const int rq = lane & 15;
                const int cq = kh * 16 + ((lane >> 4) << 3);
                uint af[2][4];
#pragma unroll
                for (int mi = 0; mi < 2; ++mi)
                    ldmx4(af[mi][0], af[mi][1], af[mi][2], af[mi][3],
                          &As[buf][wm * 32 + mi * 16 + rq][cq]);
                uint bf4[4][4];
#pragma unroll
                for (int nq = 0; nq < 4; ++nq)
                    ldmx4(bf4[nq][0], bf4[nq][1], bf4[nq][2], bf4[nq][3],
                          &Bs[buf][wn * 64 + nq * 16 + rq][cq]);
#pragma unroll
                for (int mi = 0; mi < 2; ++mi)
#pragma unroll
                    for (int nq = 0; nq < 4; ++nq) {
                        mma16816(acc[mi][2 * nq],     af[mi], bf4[nq][0], bf4[nq][2]);
                        mma16816(acc[mi][2 * nq + 1], af[mi], bf4[nq][1], bf4[nq][3]);
                    }
            }

            if (has) {
                const int nb = buf ^ 1;
                *(uint4*)&As[nb][srow][scol]     = na0;
                *(uint4*)&As[nb][srow][scol + 8] = na1;
                *(uint4*)&Bs[nb][srow][scol]     = nb0;
                *(uint4*)&Bs[nb][srow][scol + 8] = nb1;
                __syncthreads();
            }
        }
    }

    // epilogue: lane l holds c[r + {0,8}][c + {0,1}], r = l>>2, c = 2*(l&3)
    // (masked/dead rows have acc = 0 -> TANH path yields tanh(bias) naturally)
    const int r  = lane >> 2;
    const int cq = (lane & 3) * 2;
#pragma unroll
    for (int mi = 0; mi < 2; ++mi) {
#pragma unroll
        for (int nj = 0; nj < 8; ++nj) {
            const int m1 = m0 + wm * 32 + mi * 16 + r;
            const int n1 = n0 + wn * 64 + nj * 8 + cq;
            float bb0 = b1 ? __ldg(b1 + n1) : 0.f;
            float bb1 = b1 ? __ldg(b1 + n1 + 1) : 0.f;
            if (b2) { bb0 += __ldg(b2 + n1); bb1 += __ldg(b2 + n1 + 1); }
            float v0 = acc[mi][nj][0] + bb0;
            float v1 = acc[mi][nj][1] + bb1;
            float v2 = acc[mi][nj][2] + bb0;
            float v3 = acc[mi][nj][3] + bb1;
            if (TANH) { v0 = tanhf(v0); v1 = tanhf(v1); v2 = tanhf(v2); v3 = tanhf(v3); }
            *(float2*)(C + (size_t)m1 * N + n1)       = make_float2(v0, v1);
            *(float2*)(C + (size_t)(m1 + 8) * N + n1) = make_float2(v2, v3);
        }
    }
}

// ---------------- persistent LSTM layer kernel (512 threads, k-split warps) ----------------
// R10-validated memory layout (k-stride-1 lane ownership, scalar W LDG).
// Batch-quad truncation with 4/2/1 nests. Sharded ticket barrier: 8 atomic
// counters (256B apart), 16 blocks each; per-shard self-calibrating rounds.
#define FMA_NEST(QN)                                                          \
    _Pragma("unroll 1")                                                       \
    for (int j = 0; j < 4; ++j) {                                             \
        const int kb = j * 128 + lane;                                        \
        _Pragma("unroll")                                                     \
        for (int kc = 0; kc < 4; ++kc) {                                      \
            const int kk = kb + kc * 32;                                      \
            const float w0 = __ldg(w0p + kk);                                 \
            const float w1 = __ldg(w1p + kk);                                 \
            const float w2 = __ldg(w2p + kk);                                 \
            const float w3 = __ldg(w3p + kk);                                 \
            const ull wp0 = pack2(w0, w0);                                    \
            const ull wp1 = pack2(w1, w1);                                    \
            const ull wp2 = pack2(w2, w2);                                    \
            const ull wp3 = pack2(w3, w3);                                    \
            const float* hrow = hs + (koff + kk) * HSTRIDE;                   \
            _Pragma("unroll")                                                 \
            for (int bq = 0; bq < (QN); ++bq) {                               \
                const ulonglong2 h2 = *(const ulonglong2*)(hrow + bq * 4);    \
                const int i0 = (2 * bq) * 4;                                  \
                const int i1 = (2 * bq + 1) * 4;                              \
                acc[i0+0] = fma2(wp0, h2.x, acc[i0+0]);                       \
                acc[i0+1] = fma2(wp1, h2.x, acc[i0+1]);                       \
                acc[i0+2] = fma2(wp2, h2.x, acc[i0+2]);                       \
                acc[i0+3] = fma2(wp3, h2.x, acc[i0+3]);                       \
                acc[i1+0] = fma2(wp0, h2.y, acc[i1+0]);                       \
                acc[i1+1] = fma2(wp1, h2.y, acc[i1+1]);                       \
                acc[i1+2] = fma2(wp2, h2.y, acc[i1+2]);                       \
                acc[i1+3] = fma2(wp3, h2.y, acc[i1+3]);                       \
            }                                                                 \
        }                                                                     \
    }

__global__ void __launch_bounds__(512) lstm_layer_kernel(
    const float* __restrict__ Whh,   // [4096,1024]
    const float* __restrict__ xg,    // [B*T,4096]
    float* __restrict__ ys,          // [B*T,1024]
    float* __restrict__ hT,          // [1024,16]
    const int* __restrict__ ilens)
{
    extern __shared__ float hs[];                    // [1024][HSTRIDE]
    ull* comb = (ull*)(hs + CD_ * HSTRIDE);          // [8*32] flat
    const int tid  = threadIdx.x;
    const int lane = tid & 31;
    const int warp = tid >> 5;                       // 0..15
    const int wc   = warp & 7;
    const int kh   = warp >> 3;
    const int cell = blockIdx.x * 8 + wc;
    const int grp  = (blockIdx.x & 7) * 32;          // own shard slot (256B apart)

    const int koff = kh * 512;
    const float* w0p = Whh + (size_t)(0 * CD_ + cell) * CD_ + koff;
    const float* w1p = Whh + (size_t)(1 * CD_ + cell) * CD_ + koff;
    const float* w2p = Whh + (size_t)(2 * CD_ + cell) * CD_ + koff;
    const float* w3p = Whh + (size_t)(3 * CD_ + cell) * CD_ + koff;

    const int il_reg = (lane < B_) ? __ldg(ilens + lane) : 0;
    float creg = 0.f;

    for (int t = 0; t < T_; ++t) {
        const uint bal  = __ballot_sync(0xffffffffu, t < il_reg);
        const int  live = __popc(bal);               // live batches (>=1)
        const bool alive = (kh == 0) && (lane < B_) && (t < il_reg);

        float xgi = 0.f, xgf = 0.f, xgg = 0.f, xgo = 0.f;
        size_t orow = 0;
        if (alive) {
            orow = (size_t)(lane * T_ + t);
            const float* xr = xg + orow * GD_ + cell;
            xgi = __ldg(xr);
            xgf = __ldg(xr + CD_);
            xgg = __ldg(xr + 2 * CD_);
            xgo = __ldg(xr + 3 * CD_);
        }

        ull acc[32];
#pragma unroll
        for (int i = 0; i < 32; ++i) acc[i] = 0ULL;

        if (t > 0) {
            const int qn = (live > 8) ? 4 : ((live > 4) ? 2 : 1);  // staged quads
            const float4* src = (const float4*)hT;
#pragma unroll 4
            for (int i = tid; i < CD_ * B_ / 4; i += 512) {
                if ((i & 3) < qn) {
                    float4 v = __ldcg(src + i);
                    const int k  = i >> 2;
                    const int bq = (i & 3) * 4;
                    float* d = hs + k * HSTRIDE + bq;
                    d[0] = v.x; d[1] = v.y; d[2] = v.z; d[3] = v.w;
                }
            }
            __syncthreads();

            if (live > 8)      { FMA_NEST(4) }
            else if (live > 4) { FMA_NEST(2) }
            else               { FMA_NEST(1) }
        }

#pragma unroll
        for (int s = 0; s < 5; ++s) {
            const int off = 16 >> s;
            const int n   = 16 >> s;
            const bool hi = (lane & off) != 0;
#pragma unroll
            for (int i = 0; i < n; ++i) {
                ull send = hi ? acc[i] : acc[i + n];
                ull r = __shfl_xor_sync(0xffffffffu, send, off);
                acc[i] = add2(hi ? acc[i + n] : acc[i], r);
            }
        }

        if (kh == 1) comb[wc * 32 + lane] = acc[0];
        __syncthreads();
        ull tot = acc[0];
        if (kh == 0) tot = add2(tot, comb[wc * 32 + lane]);

        const int srcl = (lane >> 1) * 4;
        const ull r0 = __shfl_sync(0xffffffffu, tot, srcl + 0);
        const ull r1 = __shfl_sync(0xffffffffu, tot, srcl + 1);
        const ull r2 = __shfl_sync(0xffffffffu, tot, srcl + 2);
        const ull r3 = __shfl_sync(0xffffffffu, tot, srcl + 3);

        if (alive) {
            const bool oddb = (lane & 1) != 0;
            const float2 p0 = unpack2(r0), p1 = unpack2(r1), p2 = unpack2(r2), p3 = unpack2(r3);
            const float gi = (oddb ? p0.y : p0.x) + xgi;
            const float gf = (oddb ? p1.y : p1.x) + xgf;
            const float gg = (oddb ? p2.y : p2.x) + xgg;
            const float go = (oddb ? p3.y : p3.x) + xgo;
            const float cn = sigf(gf) * creg + sigf(gi) * tanhf(gg);
            creg = cn;
            const float hn = sigf(go) * tanhf(cn);
            ys[orow * CD_ + cell] = hn;
            hT[cell * B_ + lane]  = hn;
        }

        // ---- sharded grid ticket barrier (monotonic, replay-safe) ----
        // arrive on own shard (16 blocks each); round r = x>>4 is the global
        // step index; everyone waits until ALL 8 shards reach 16*(r+1).
        __threadfence();
        __syncthreads();
        if (tid == 0) {
            ull x = atomicAdd(&g_cnt8[grp], 1ULL);
            ull need = ((x >> 4) + 1ULL) << 4;
#pragma unroll 1
            for (int c = 0; c < 8; ++c)
                while (*(volatile ull*)&g_cnt8[c * 32] < need) { }
        }
        __syncthreads();
    }
}

// ---------------- ilens tail ----------------
__global__ void write_tail_kernel(float* __restrict__ out, const int* __restrict__ ilens,
                                  long long base, long long out_size) {
    int i = threadIdx.x;
    if (i < B_ && base + i < out_size) out[base + i] = (float)ilens[i];
}

// ---------------- launch ----------------
extern "C" void kernel_launch(void* const* d_in, const int* in_sizes, int n_in,
                              void* d_out, int out_size)
{
    const float* xpad  = (const float*)d_in[0];   // [B,T,IDIM]
    const float* Wih0  = (const float*)d_in[1];   // [4096,320]
    const float* WihR  = (const float*)d_in[2];   // [3,4096,1024]
    const float* Whh   = (const float*)d_in[3];   // [4,4096,1024]
    const float* bih   = (const float*)d_in[4];   // [4,4096]
    const float* bhh   = (const float*)d_in[5];   // [4,4096]
    const float* Wlast = (const float*)d_in[6];   // [1024,1024]
    const float* blast = (const float*)d_in[7];   // [1024]
    const int*   ilens = (const int*)d_in[8];     // [16]
    float* out = (float*)d_out;

    float *xg, *xb, *hT;
    __nv_bfloat16 *ah, *al, *bh, *bl;
    cudaGetSymbolAddress((void**)&xg, g_xg);
    cudaGetSymbolAddress((void**)&xb, g_x);
    cudaGetSymbolAddress((void**)&hT, g_hT);
    cudaGetSymbolAddress((void**)&ah, g_ah);
    cudaGetSymbolAddress((void**)&al, g_al);
    cudaGetSymbolAddress((void**)&bh, g_bh);
    cudaGetSymbolAddress((void**)&bl, g_bl);

    const int smem_step = CD_ * HSTRIDE * 4 + 8 * 32 * 8;  // 81920 + 2048
    cudaFuncSetAttribute(lstm_layer_kernel,
                         cudaFuncAttributeMaxDynamicSharedMemorySize, smem_step);

    const int M = B_ * T_;  // 8192

    for (int l = 0; l < LAYERS_; ++l) {
        const float* Ain = (l == 0) ? xpad : xb;
        const float* Bw  = (l == 0) ? Wih0 : (WihR + (size_t)(l - 1) * GD_ * CD_);
        const int K = (l == 0) ? IDIM_ : CD_;

        {
            int nA = M * K;
            conv_split_kernel<<<(nA / 2 + 255) / 256, 256>>>(Ain, ah, al, nA, K, nullptr);
            int nB = GD_ * K;
            conv_split_kernel<<<(nB / 2 + 255) / 256, 256>>>(Bw, bh, bl, nB, K, nullptr);
        }

        dim3 grid_xg(GD_ / 128, M / 128);
        gemm_bf16x3_kernel<0><<<grid_xg, 256>>>(ah, al, bh, bl,
                                                bih + l * GD_, bhh + l * GD_,
                                                xg, M, GD_, K, ilens);

        const float* Wl = Whh + (size_t)l * GD_ * CD_;
        lstm_layer_kernel<<<NBLK_, 512, smem_step>>>(Wl, xg, xb, hT, ilens);
    }

    // projection: conv masks dead rows (acc=0 -> tanh(bias)); dead tiles skip mainloop
    {
        int nA = M * CD_;
        conv_split_kernel<<<(nA / 2 + 255) / 256, 256>>>(xb, ah, al, nA, CD_, ilens);
        int nB = HD_ * CD_;
        conv_split_kernel<<<(nB / 2 + 255) / 256, 256>>>(Wlast, bh, bl, nB, CD_, nullptr);
        dim3 grid_p(HD_ / 128, M / 128);
        gemm_bf16x3_kernel<1><<<grid_p, 256>>>(ah, al, bh, bl, blast, nullptr,
                                               out, M, HD_, CD_, ilens);
    }

    const long long base = (long long)B_ * T_ * HD_;  // 8388608
    if ((long long)out_size > base)
        write_tail_kernel<<<1, 32>>>(out, ilens, base, (long long)out_size);
}

// round 15
// speedup vs baseline: 1.4202x; 1.2502x over previous
#include <cuda_runtime.h>
#include <cuda_bf16.h>
#include <math.h>
#include <cstdint>

#define B_ 16
#define T_ 512
#define IDIM_ 320
#define CD_ 1024
#define GD_ 4096   // 4*CD
#define HD_ 1024
#define LAYERS_ 4
#define NBLK_ 128  // persistent grid: <= 148 SMs -> all co-resident

typedef unsigned long long ull;
typedef unsigned int uint;

// ---------------- scratch (static device globals; no runtime alloc) ----------------
__device__ float g_xg[(size_t)B_ * T_ * GD_];        // precomputed input gates
__device__ float g_x [(size_t)B_ * T_ * CD_];        // layer io buffer (ys)
__device__ float g_hT[CD_ * B_];                     // h transposed: hT[cell][b]
__device__ ull   g_shard[16 * 32];                   // 16 arrival shards (256B apart)
__device__ ull   g_done;                             // global round counter (+16/step)
__device__ __align__(16) __nv_bfloat16 g_ah[(size_t)B_ * T_ * CD_]; // A hi
__device__ __align__(16) __nv_bfloat16 g_al[(size_t)B_ * T_ * CD_]; // A lo
__device__ __align__(16) __nv_bfloat16 g_bh[(size_t)GD_ * CD_];     // B hi
__device__ __align__(16) __nv_bfloat16 g_bl[(size_t)GD_ * CD_];     // B lo

// ---------------- packed fp32x2 helpers (step kernel) ----------------
__device__ __forceinline__ ull fma2(ull a, ull b, ull c) {
    ull d;
    asm("fma.rn.f32x2 %0, %1, %2, %3;" : "=l"(d) : "l"(a), "l"(b), "l"(c));
    return d;
}
__device__ __forceinline__ ull add2(ull a, ull b) {
    ull d;
    asm("add.rn.f32x2 %0, %1, %2;" : "=l"(d) : "l"(a), "l"(b));
    return d;
}
__device__ __forceinline__ ull pack2(float x, float y) {
    ull d;
    asm("mov.b64 %0, {%1, %2};" : "=l"(d) : "f"(x), "f"(y));
    return d;
}
__device__ __forceinline__ float2 unpack2(ull v) {
    float2 r;
    asm("mov.b64 {%0, %1}, %2;" : "=f"(r.x), "=f"(r.y) : "l"(v));
    return r;
}
__device__ __forceinline__ float sigf(float x) { return 1.f / (1.f + expf(-x)); }

#define HSTRIDE 20   // padded row stride (floats) for transposed h in smem

// ---------------- bf16 split conversion ----------------
// hi = bf16(x); lo = bf16(x - hi). Optional mask: zero rows with t >= ilens[b].
__global__ void __launch_bounds__(256) conv_split_kernel(
    const float* __restrict__ x, __nv_bfloat16* __restrict__ hi,
    __nv_bfloat16* __restrict__ lo, int n, int K, const int* __restrict__ ilens)
{
    int i = (blockIdx.x * 256 + threadIdx.x) * 2;
    if (i >= n) return;
    float2 v = *(const float2*)(x + i);
    if (ilens) {
        int m = i / K;
        int t = m & (T_ - 1);
        int b = m >> 9;
        if (t >= ilens[b]) { v.x = 0.f; v.y = 0.f; }
    }
    __nv_bfloat162 h2, l2;
    h2.x = __float2bfloat16_rn(v.x);
    h2.y = __float2bfloat16_rn(v.y);
    l2.x = __float2bfloat16_rn(v.x - __bfloat162float(h2.x));
    l2.y = __float2bfloat16_rn(v.y - __bfloat162float(h2.y));
    *(__nv_bfloat162*)(hi + i) = h2;
    *(__nv_bfloat162*)(lo + i) = l2;
}

// ---------------- MMA helpers ----------------
__device__ __forceinline__ void ldmx4(uint& r0, uint& r1, uint& r2, uint& r3,
                                      const __nv_bfloat16* p) {
    uint a = (uint)__cvta_generic_to_shared(p);
    asm volatile("ldmatrix.sync.aligned.m8n8.x4.shared.b16 {%0,%1,%2,%3}, [%4];"
                 : "=r"(r0), "=r"(r1), "=r"(r2), "=r"(r3) : "r"(a));
}
__device__ __forceinline__ void mma16816(float* d, const uint* a, uint b0, uint b1) {
    asm volatile(
        "mma.sync.aligned.m16n8k16.row.col.f32.bf16.bf16.f32 "
        "{%0,%1,%2,%3}, {%4,%5,%6,%7}, {%8,%9}, {%0,%1,%2,%3};"
        : "+f"(d[0]), "+f"(d[1]), "+f"(d[2]), "+f"(d[3])
        : "r"(a[0]), "r"(a[1]), "r"(a[2]), "r"(a[3]), "r"(b0), "r"(b1));
}

// ---------------- bf16x3 GEMM (NT): C = A*B^T + bias, fp32 accum ----------------
// R5-validated structure: 128x128x32 tiles, 256 threads, 8 warps (4M x 2N,
// warp 32x64), register-prefetch ping-pong smem, ONE sync per slab.
// Virtual K'' = 3K over segments (Ah,Bh),(Al,Bh),(Ah,Bl).
// Dead tiles (t0 >= ilens[b]): TANH=0 return; TANH=1 skip mainloop -> tanh(bias).
#define SPAD 40  // bf16 row stride (32 + 8 pad): conflict-free ldmatrix phases
template <int TANH>
__global__ void __launch_bounds__(256) gemm_bf16x3_kernel(
    const __nv_bfloat16* __restrict__ Ah, const __nv_bfloat16* __restrict__ Al,
    const __nv_bfloat16* __restrict__ Bh, const __nv_bfloat16* __restrict__ Bl,
    const float* __restrict__ b1, const float* __restrict__ b2,
    float* __restrict__ C, int M, int N, int K, const int* __restrict__ ilens)
{
    __shared__ __align__(16) __nv_bfloat16 As[2][128][SPAD];
    __shared__ __align__(16) __nv_bfloat16 Bs[2][128][SPAD];

    const int tid  = threadIdx.x;
    const int m0   = blockIdx.y * 128;
    const int n0   = blockIdx.x * 128;
    const int srow = tid >> 1;           // staging: row 0..127
    const int scol = (tid & 1) * 16;     // staging: k offset 0 or 16
    const int lane = tid & 31;
    const int warp = tid >> 5;
    const int wm   = warp & 3;           // 4 warps along M (32 rows each)
    const int wn   = warp >> 2;          // 2 warps along N (64 cols each)

    const bool tdead = ((m0 & 511) >= __ldg(ilens + (m0 >> 9)));
    if (!TANH && tdead) return;

    const int perseg = K >> 5;           // slabs per segment
    const int nslab  = 3 * perseg;

    float acc[2][8][4];
#pragma unroll
    for (int i = 0; i < 2; ++i)
#pragma unroll
        for (int j = 0; j < 8; ++j)
#pragma unroll
            for (int q = 0; q < 4; ++q) acc[i][j][q] = 0.f;

    if (!tdead) {
        auto srcA = [&](int s) -> const uint4* {
            int seg = s / perseg, kin = (s - seg * perseg) * 32;
            const __nv_bfloat16* A = (seg == 1) ? Al : Ah;
            return (const uint4*)(A + (size_t)(m0 + srow) * K + kin + scol);
        };
        auto srcB = [&](int s) -> const uint4* {
            int seg = s / perseg, kin = (s - seg * perseg) * 32;
            const __nv_bfloat16* Bp = (seg == 2) ? Bl : Bh;
            return (const uint4*)(Bp + (size_t)(n0 + srow) * K + kin + scol);
        };

        // prologue: slab 0 -> buffer 0
        {
            const uint4* pa = srcA(0);
            const uint4* pb = srcB(0);
            uint4 a0 = pa[0], a1 = pa[1], bq0 = pb[0], bq1 = pb[1];
            *(uint4*)&As[0][srow][scol]     = a0;
            *(uint4*)&As[0][srow][scol + 8] = a1;
            *(uint4*)&Bs[0][srow][scol]     = bq0;
            *(uint4*)&Bs[0][srow][scol + 8] = bq1;
        }
        __syncthreads();

        for (int s = 0; s < nslab; ++s) {
            const int buf = s & 1;
            const bool has = (s + 1) < nslab;
            uint4 na0, na1, nb0, nb1;
            if (has) {
                const uint4* pa = srcA(s + 1);
                const uint4* pb = srcB(s + 1);
                na0 = pa[0]; na1 = pa[1]; nb0 = pb[0]; nb1 = pb[1];
            }

#pragma unroll
            for (int kh = 0; kh < 2; ++kh) {
                const int rq = lane & 15;
                const int cq = kh * 16 + ((lane >> 4) << 3);
                uint af[2][4];
#pragma unroll
                for (int mi = 0; mi < 2; ++mi)
                    ldmx4(af[mi][0], af[mi][1], af[mi][2], af[mi][3],
                          &As[buf][wm * 32 + mi * 16 + rq][cq]);
                uint bf4[4][4];
#pragma unroll
                for (int nq = 0; nq < 4; ++nq)
                    ldmx4(bf4[nq][0], bf4[nq][1], bf4[nq][2], bf4[nq][3],
                          &Bs[buf][wn * 64 + nq * 16 + rq][cq]);
#pragma unroll
                for (int mi = 0; mi < 2; ++mi)
#pragma unroll
                    for (int nq = 0; nq < 4; ++nq) {
                        mma16816(acc[mi][2 * nq],     af[mi], bf4[nq][0], bf4[nq][2]);
                        mma16816(acc[mi][2 * nq + 1], af[mi], bf4[nq][1], bf4[nq][3]);
                    }
            }

            if (has) {
                const int nb = buf ^ 1;
                *(uint4*)&As[nb][srow][scol]     = na0;
                *(uint4*)&As[nb][srow][scol + 8] = na1;
                *(uint4*)&Bs[nb][srow][scol]     = nb0;
                *(uint4*)&Bs[nb][srow][scol + 8] = nb1;
                __syncthreads();
            }
        }
    }

    // epilogue: lane l holds c[r + {0,8}][c + {0,1}], r = l>>2, c = 2*(l&3)
    // (masked/dead rows have acc = 0 -> TANH path yields tanh(bias) naturally)
    const int r  = lane >> 2;
    const int cq = (lane & 3) * 2;
#pragma unroll
    for (int mi = 0; mi < 2; ++mi) {
#pragma unroll
        for (int nj = 0; nj < 8; ++nj) {
            const int m1 = m0 + wm * 32 + mi * 16 + r;
            const int n1 = n0 + wn * 64 + nj * 8 + cq;
            float bb0 = b1 ? __ldg(b1 + n1) : 0.f;
            float bb1 = b1 ? __ldg(b1 + n1 + 1) : 0.f;
            if (b2) { bb0 += __ldg(b2 + n1); bb1 += __ldg(b2 + n1 + 1); }
            float v0 = acc[mi][nj][0] + bb0;
            float v1 = acc[mi][nj][1] + bb1;
            float v2 = acc[mi][nj][2] + bb0;
            float v3 = acc[mi][nj][3] + bb1;
            if (TANH) { v0 = tanhf(v0); v1 = tanhf(v1); v2 = tanhf(v2); v3 = tanhf(v3); }
            *(float2*)(C + (size_t)m1 * N + n1)       = make_float2(v0, v1);
            *(float2*)(C + (size_t)(m1 + 8) * N + n1) = make_float2(v2, v3);
        }
    }
}

// ---------------- persistent LSTM layer kernel (512 threads, k-split warps) ----------------
// R10-validated memory layout (k-stride-1 lane ownership, scalar W LDG).
// Batch-quad truncation with 4/2/1 nests. Hierarchical ticket barrier:
// 16 arrival shards (8 blocks each) + single global round counter for the wait.
#define FMA_NEST(QN)                                                          \
    _Pragma("unroll 1")                                                       \
    for (int j = 0; j < 4; ++j) {                                             \
        const int kb = j * 128 + lane;                                        \
        _Pragma("unroll")                                                     \
        for (int kc = 0; kc < 4; ++kc) {                                      \
            const int kk = kb + kc * 32;                                      \
            const float w0 = __ldg(w0p + kk);                                 \
            const float w1 = __ldg(w1p + kk);                                 \
            const float w2 = __ldg(w2p + kk);                                 \
            const float w3 = __ldg(w3p + kk);                                 \
            const ull wp0 = pack2(w0, w0);                                    \
            const ull wp1 = pack2(w1, w1);                                    \
            const ull wp2 = pack2(w2, w2);                                    \
            const ull wp3 = pack2(w3, w3);                                    \
            const float* hrow = hs + (koff + kk) * HSTRIDE;                   \
            _Pragma("unroll")                                                 \
            for (int bq = 0; bq < (QN); ++bq) {                               \
                const ulonglong2 h2 = *(const ulonglong2*)(hrow + bq * 4);    \
                const int i0 = (2 * bq) * 4;                                  \
                const int i1 = (2 * bq + 1) * 4;                              \
                acc[i0+0] = fma2(wp0, h2.x, acc[i0+0]);                       \
                acc[i0+1] = fma2(wp1, h2.x, acc[i0+1]);                       \
                acc[i0+2] = fma2(wp2, h2.x, acc[i0+2]);                       \
                acc[i0+3] = fma2(wp3, h2.x, acc[i0+3]);                       \
                acc[i1+0] = fma2(wp0, h2.y, acc[i1+0]);                       \
                acc[i1+1] = fma2(wp1, h2.y, acc[i1+1]);                       \
                acc[i1+2] = fma2(wp2, h2.y, acc[i1+2]);                       \
                acc[i1+3] = fma2(wp3, h2.y, acc[i1+3]);                       \
            }                                                                 \
        }                                                                     \
    }

__global__ void __launch_bounds__(512) lstm_layer_kernel(
    const float* __restrict__ Whh,   // [4096,1024]
    const float* __restrict__ xg,    // [B*T,4096]
    float* __restrict__ ys,          // [B*T,1024]
    float* __restrict__ hT,          // [1024,16]
    const int* __restrict__ ilens)
{
    extern __shared__ float hs[];                    // [1024][HSTRIDE]
    ull* comb = (ull*)(hs + CD_ * HSTRIDE);          // [8*32] flat
    const int tid  = threadIdx.x;
    const int lane = tid & 31;
    const int warp = tid >> 5;                       // 0..15
    const int wc   = warp & 7;
    const int kh   = warp >> 3;
    const int cell = blockIdx.x * 8 + wc;
    const int sh   = (blockIdx.x & 15) * 32;         // arrival shard slot (256B apart)

    const int koff = kh * 512;
    const float* w0p = Whh + (size_t)(0 * CD_ + cell) * CD_ + koff;
    const float* w1p = Whh + (size_t)(1 * CD_ + cell) * CD_ + koff;
    const float* w2p = Whh + (size_t)(2 * CD_ + cell) * CD_ + koff;
    const float* w3p = Whh + (size_t)(3 * CD_ + cell) * CD_ + koff;

    const int il_reg = (lane < B_) ? __ldg(ilens + lane) : 0;
    float creg = 0.f;

    for (int t = 0; t < T_; ++t) {
        const uint bal  = __ballot_sync(0xffffffffu, t < il_reg);
        const int  live = __popc(bal);               // live batches (>=1)
        const bool alive = (kh == 0) && (lane < B_) && (t < il_reg);

        float xgi = 0.f, xgf = 0.f, xgg = 0.f, xgo = 0.f;
        size_t orow = 0;
        if (alive) {
            orow = (size_t)(lane * T_ + t);
            const float* xr = xg + orow * GD_ + cell;
            xgi = __ldg(xr);
            xgf = __ldg(xr + CD_);
            xgg = __ldg(xr + 2 * CD_);
            xgo = __ldg(xr + 3 * CD_);
        }

        ull acc[32];
#pragma unroll
        for (int i = 0; i < 32; ++i) acc[i] = 0ULL;

        if (t > 0) {
            const int qn = (live > 8) ? 4 : ((live > 4) ? 2 : 1);  // staged quads
            const float4* src = (const float4*)hT;
#pragma unroll 4
            for (int i = tid; i < CD_ * B_ / 4; i += 512) {
                if ((i & 3) < qn) {
                    float4 v = __ldcg(src + i);
                    const int k  = i >> 2;
                    const int bq = (i & 3) * 4;
                    float* d = hs + k * HSTRIDE + bq;
                    d[0] = v.x; d[1] = v.y; d[2] = v.z; d[3] = v.w;
                }
            }
            __syncthreads();

            if (live > 8)      { FMA_NEST(4) }
            else if (live > 4) { FMA_NEST(2) }
            else               { FMA_NEST(1) }
        }

#pragma unroll
        for (int s = 0; s < 5; ++s) {
            const int off = 16 >> s;
            const int n   = 16 >> s;
            const bool hi = (lane & off) != 0;
#pragma unroll
            for (int i = 0; i < n; ++i) {
                ull send = hi ? acc[i] : acc[i + n];
                ull r = __shfl_xor_sync(0xffffffffu, send, off);
                acc[i] = add2(hi ? acc[i + n] : acc[i], r);
            }
        }

        if (kh == 1) comb[wc * 32 + lane] = acc[0];
        __syncthreads();
        ull tot = acc[0];
        if (kh == 0) tot = add2(tot, comb[wc * 32 + lane]);

        const int srcl = (lane >> 1) * 4;
        const ull r0 = __shfl_sync(0xffffffffu, tot, srcl + 0);
        const ull r1 = __shfl_sync(0xffffffffu, tot, srcl + 1);
        const ull r2 = __shfl_sync(0xffffffffu, tot, srcl + 2);
        const ull r3 = __shfl_sync(0xffffffffu, tot, srcl + 3);

        if (alive) {
            const bool oddb = (lane & 1) != 0;
            const float2 p0 = unpack2(r0), p1 = unpack2(r1), p2 = unpack2(r2), p3 = unpack2(r3);
            const float gi = (oddb ? p0.y : p0.x) + xgi;
            const float gf = (oddb ? p1.y : p1.x) + xgf;
            const float gg = (oddb ? p2.y : p2.x) + xgg;
            const float go = (oddb ? p3.y : p3.x) + xgo;
            const float cn = sigf(gf) * creg + sigf(gi) * tanhf(gg);
            creg = cn;
            const float hn = sigf(go) * tanhf(cn);
            ys[orow * CD_ + cell] = hn;
            hT[cell * B_ + lane]  = hn;
        }

        // ---- hierarchical grid ticket barrier (monotonic, replay-safe) ----
        // arrive on own shard (8 blocks each); the 8th arriver of the round
        // bumps g_done; EVERYONE waits on the single g_done line.
        __threadfence();
        __syncthreads();
        if (tid == 0) {
            ull x = atomicAdd(&g_shard[sh], 1ULL);
            if ((x & 7ULL) == 7ULL) atomicAdd(&g_done, 1ULL);
            ull need = ((x >> 3) + 1ULL) << 4;   // 16 shard-completions per round
            while (*(volatile ull*)&g_done < need) { }
        }
        __syncthreads();
    }
}

// ---------------- ilens tail ----------------
__global__ void write_tail_kernel(float* __restrict__ out, const int* __restrict__ ilens,
                                  long long base, long long out_size) {
    int i = threadIdx.x;
    if (i < B_ && base + i < out_size) out[base + i] = (float)ilens[i];
}

// ---------------- launch ----------------
extern "C" void kernel_launch(void* const* d_in, const int* in_sizes, int n_in,
                              void* d_out, int out_size)
{
    const float* xpad  = (const float*)d_in[0];   // [B,T,IDIM]
    const float* Wih0  = (const float*)d_in[1];   // [4096,320]
    const float* WihR  = (const float*)d_in[2];   // [3,4096,1024]
    const float* Whh   = (const float*)d_in[3];   // [4,4096,1024]
    const float* bih   = (const float*)d_in[4];   // [4,4096]
    const float* bhh   = (const float*)d_in[5];   // [4,4096]
    const float* Wlast = (const float*)d_in[6];   // [1024,1024]
    const float* blast = (const float*)d_in[7];   // [1024]
    const int*   ilens = (const int*)d_in[8];     // [16]
    float* out = (float*)d_out;

    float *xg, *xb, *hT;
    __nv_bfloat16 *ah, *al, *bh, *bl;
    cudaGetSymbolAddress((void**)&xg, g_xg);
    cudaGetSymbolAddress((void**)&xb, g_x);
    cudaGetSymbolAddress((void**)&hT, g_hT);
    cudaGetSymbolAddress((void**)&ah, g_ah);
    cudaGetSymbolAddress((void**)&al, g_al);
    cudaGetSymbolAddress((void**)&bh, g_bh);
    cudaGetSymbolAddress((void**)&bl, g_bl);

    const int smem_step = CD_ * HSTRIDE * 4 + 8 * 32 * 8;  // 81920 + 2048
    cudaFuncSetAttribute(lstm_layer_kernel,
                         cudaFuncAttributeMaxDynamicSharedMemorySize, smem_step);

    const int M = B_ * T_;  // 8192

    for (int l = 0; l < LAYERS_; ++l) {
        const float* Ain = (l == 0) ? xpad : xb;
        const float* Bw  = (l == 0) ? Wih0 : (WihR + (size_t)(l - 1) * GD_ * CD_);
        const int K = (l == 0) ? IDIM_ : CD_;

        {
            int nA = M * K;
            conv_split_kernel<<<(nA / 2 + 255) / 256, 256>>>(Ain, ah, al, nA, K, nullptr);
            int nB = GD_ * K;
            conv_split_kernel<<<(nB / 2 + 255) / 256, 256>>>(Bw, bh, bl, nB, K, nullptr);
        }

        dim3 grid_xg(GD_ / 128, M / 128);
        gemm_bf16x3_kernel<0><<<grid_xg, 256>>>(ah, al, bh, bl,
                                                bih + l * GD_, bhh + l * GD_,
                                                xg, M, GD_, K, ilens);

        const float* Wl = Whh + (size_t)l * GD_ * CD_;
        lstm_layer_kernel<<<NBLK_, 512, smem_step>>>(Wl, xg, xb, hT, ilens);
    }

    // projection: conv masks dead rows (acc=0 -> tanh(bias)); dead tiles skip mainloop
    {
        int nA = M * CD_;
        conv_split_kernel<<<(nA / 2 + 255) / 256, 256>>>(xb, ah, al, nA, CD_, ilens);
        int nB = HD_ * CD_;
        conv_split_kernel<<<(nB / 2 + 255) / 256, 256>>>(Wlast, bh, bl, nB, CD_, nullptr);
        dim3 grid_p(HD_ / 128, M / 128);
        gemm_bf16x3_kernel<1><<<grid_p, 256>>>(ah, al, bh, bl, blast, nullptr,
                                               out, M, HD_, CD_, ilens);
    }

    const long long base = (long long)B_ * T_ * HD_;  // 8388608
    if ((long long)out_size > base)
        write_tail_kernel<<<1, 32>>>(out, ilens, base, (long long)out_size);
}

// round 16
// speedup vs baseline: 1.4855x; 1.0460x over previous
#include <cuda_runtime.h>
#include <cuda_bf16.h>
#include <math.h>
#include <cstdint>

#define B_ 16
#define T_ 512
#define IDIM_ 320
#define CD_ 1024
#define GD_ 4096   // 4*CD
#define HD_ 1024
#define LAYERS_ 4
#define NBLK_ 128  // persistent grid: <= 148 SMs -> all co-resident

typedef unsigned long long ull;
typedef unsigned int uint;

// ---------------- scratch (static device globals; no runtime alloc) ----------------
__device__ float g_xg[(size_t)B_ * T_ * GD_];        // precomputed input gates
__device__ float g_x [(size_t)B_ * T_ * CD_];        // layer io buffer (ys)
__device__ float g_hT[CD_ * B_];                     // h transposed: hT[cell][b]
__device__ ull   g_bar;                              // ticket barrier (monotonic)
__device__ __align__(16) __nv_bfloat16 g_ah[(size_t)B_ * T_ * CD_]; // A hi
__device__ __align__(16) __nv_bfloat16 g_al[(size_t)B_ * T_ * CD_]; // A lo
__device__ __align__(16) __nv_bfloat16 g_bh[(size_t)GD_ * CD_];     // B hi
__device__ __align__(16) __nv_bfloat16 g_bl[(size_t)GD_ * CD_];     // B lo

// ---------------- packed fp32x2 helpers (step kernel) ----------------
__device__ __forceinline__ ull fma2(ull a, ull b, ull c) {
    ull d;
    asm("fma.rn.f32x2 %0, %1, %2, %3;" : "=l"(d) : "l"(a), "l"(b), "l"(c));
    return d;
}
__device__ __forceinline__ ull add2(ull a, ull b) {
    ull d;
    asm("add.rn.f32x2 %0, %1, %2;" : "=l"(d) : "l"(a), "l"(b));
    return d;
}
__device__ __forceinline__ ull pack2(float x, float y) {
    ull d;
    asm("mov.b64 %0, {%1, %2};" : "=l"(d) : "f"(x), "f"(y));
    return d;
}
__device__ __forceinline__ float2 unpack2(ull v) {
    float2 r;
    asm("mov.b64 {%0, %1}, %2;" : "=f"(r.x), "=f"(r.y) : "l"(v));
    return r;
}
__device__ __forceinline__ float sigf(float x) { return 1.f / (1.f + expf(-x)); }

// release-scoped ticket arrive: orders all prior (bar-ordered) writes at gpu scope
__device__ __forceinline__ ull arrive_release(ull* ctr) {
    ull x;
    asm volatile("atom.release.gpu.global.add.u64 %0, [%1], %2;"
                 : "=l"(x) : "l"(ctr), "l"(1ULL) : "memory");
    return x;
}

#define HSTRIDE 20   // padded row stride (floats) for transposed h in smem

// ---------------- bf16 split conversion ----------------
// hi = bf16(x); lo = bf16(x - hi). Optional mask: zero rows with t >= ilens[b].
__global__ void __launch_bounds__(256) conv_split_kernel(
    const float* __restrict__ x, __nv_bfloat16* __restrict__ hi,
    __nv_bfloat16* __restrict__ lo, int n, int K, const int* __restrict__ ilens)
{
    int i = (blockIdx.x * 256 + threadIdx.x) * 2;
    if (i >= n) return;
    float2 v = *(const float2*)(x + i);
    if (ilens) {
        int m = i / K;
        int t = m & (T_ - 1);
        int b = m >> 9;
        if (t >= ilens[b]) { v.x = 0.f; v.y = 0.f; }
    }
    __nv_bfloat162 h2, l2;
    h2.x = __float2bfloat16_rn(v.x);
    h2.y = __float2bfloat16_rn(v.y);
    l2.x = __float2bfloat16_rn(v.x - __bfloat162float(h2.x));
    l2.y = __float2bfloat16_rn(v.y - __bfloat162float(h2.y));
    *(__nv_bfloat162*)(hi + i) = h2;
    *(__nv_bfloat162*)(lo + i) = l2;
}

// ---------------- MMA helpers ----------------
__device__ __forceinline__ void ldmx4(uint& r0, uint& r1, uint& r2, uint& r3,
                                      const __nv_bfloat16* p) {
    uint a = (uint)__cvta_generic_to_shared(p);
    asm volatile("ldmatrix.sync.aligned.m8n8.x4.shared.b16 {%0,%1,%2,%3}, [%4];"
                 : "=r"(r0), "=r"(r1), "=r"(r2), "=r"(r3) : "r"(a));
}
__device__ __forceinline__ void mma16816(float* d, const uint* a, uint b0, uint b1) {
    asm volatile(
        "mma.sync.aligned.m16n8k16.row.col.f32.bf16.bf16.f32 "
        "{%0,%1,%2,%3}, {%4,%5,%6,%7}, {%8,%9}, {%0,%1,%2,%3};"
        : "+f"(d[0]), "+f"(d[1]), "+f"(d[2]), "+f"(d[3])
        : "r"(a[0]), "r"(a[1]), "r"(a[2]), "r"(a[3]), "r"(b0), "r"(b1));
}

// ---------------- bf16x3 GEMM (NT): C = A*B^T + bias, fp32 accum ----------------
// R5-validated structure: 128x128x32 tiles, 256 threads, 8 warps (4M x 2N,
// warp 32x64), register-prefetch ping-pong smem, ONE sync per slab.
// Virtual K'' = 3K over segments (Ah,Bh),(Al,Bh),(Ah,Bl).
// Dead tiles (t0 >= ilens[b]): TANH=0 return; TANH=1 skip mainloop -> tanh(bias).
#define SPAD 40  // bf16 row stride (32 + 8 pad): conflict-free ldmatrix phases
template <int TANH>
__global__ void __launch_bounds__(256) gemm_bf16x3_kernel(
    const __nv_bfloat16* __restrict__ Ah, const __nv_bfloat16* __restrict__ Al,
    const __nv_bfloat16* __restrict__ Bh, const __nv_bfloat16* __restrict__ Bl,
    const float* __restrict__ b1, const float* __restrict__ b2,
    float* __restrict__ C, int M, int N, int K, const int* __restrict__ ilens)
{
    __shared__ __align__(16) __nv_bfloat16 As[2][128][SPAD];
    __shared__ __align__(16) __nv_bfloat16 Bs[2][128][SPAD];

    const int tid  = threadIdx.x;
    const int m0   = blockIdx.y * 128;
    const int n0   = blockIdx.x * 128;
    const int srow = tid >> 1;           // staging: row 0..127
    const int scol = (tid & 1) * 16;     // staging: k offset 0 or 16
    const int lane = tid & 31;
    const int warp = tid >> 5;
    const int wm   = warp & 3;           // 4 warps along M (32 rows each)
    const int wn   = warp >> 2;          // 2 warps along N (64 cols each)

    const bool tdead = ((m0 & 511) >= __ldg(ilens + (m0 >> 9)));
    if (!TANH && tdead) return;

    const int perseg = K >> 5;           // slabs per segment
    const int nslab  = 3 * perseg;

    float acc[2][8][4];
#pragma unroll
    for (int i = 0; i < 2; ++i)
#pragma unroll
        for (int j = 0; j < 8; ++j)
#pragma unroll
            for (int q = 0; q < 4; ++q) acc[i][j][q] = 0.f;

    if (!tdead) {
        auto srcA = [&](int s) -> const uint4* {
            int seg = s / perseg, kin = (s - seg * perseg) * 32;
            const __nv_bfloat16* A = (seg == 1) ? Al : Ah;
            return (const uint4*)(A + (size_t)(m0 + srow) * K + kin + scol);
        };
        auto srcB = [&](int s) -> const uint4* {
            int seg = s / perseg, kin = (s - seg * perseg) * 32;
            const __nv_bfloat16* Bp = (seg == 2) ? Bl : Bh;
            return (const uint4*)(Bp + (size_t)(n0 + srow) * K + kin + scol);
        };

        // prologue: slab 0 -> buffer 0
        {
            const uint4* pa = srcA(0);
            const uint4* pb = srcB(0);
            uint4 a0 = pa[0], a1 = pa[1], bq0 = pb[0], bq1 = pb[1];
            *(uint4*)&As[0][srow][scol]     = a0;
            *(uint4*)&As[0][srow][scol + 8] = a1;
            *(uint4*)&Bs[0][srow][scol]     = bq0;
            *(uint4*)&Bs[0][srow][scol + 8] = bq1;
        }
        __syncthreads();

        for (int s = 0; s < nslab; ++s) {
            const int buf = s & 1;
            const bool has = (s + 1) < nslab;
            uint4 na0, na1, nb0, nb1;
            if (has) {
                const uint4* pa = srcA(s + 1);
                const uint4* pb = srcB(s + 1);
                na0 = pa[0]; na1 = pa[1]; nb0 = pb[0]; nb1 = pb[1];
            }

#pragma unroll
            for (int kh = 0; kh < 2; ++kh) {
                const int rq = lane & 15;
                const int cq = kh * 16 + ((lane >> 4) << 3);
                uint af[2][4];
#pragma unroll
                for (int mi = 0; mi < 2; ++mi)
                    ldmx4(af[mi][0], af[mi][1], af[mi][2], af[mi][3],
                          &As[buf][wm * 32 + mi * 16 + rq][cq]);
                uint bf4[4][4];
#pragma unroll
                for (int nq = 0; nq < 4; ++nq)
                    ldmx4(bf4[nq][0], bf4[nq][1], bf4[nq][2], bf4[nq][3],
                          &Bs[buf][wn * 64 + nq * 16 + rq][cq]);
#pragma unroll
                for (int mi = 0; mi < 2; ++mi)
#pragma unroll
                    for (int nq = 0; nq < 4; ++nq) {
                        mma16816(acc[mi][2 * nq],     af[mi], bf4[nq][0], bf4[nq][2]);
                        mma16816(acc[mi][2 * nq + 1], af[mi], bf4[nq][1], bf4[nq][3]);
                    }
            }

            if (has) {
                const int nb = buf ^ 1;
                *(uint4*)&As[nb][srow][scol]     = na0;
                *(uint4*)&As[nb][srow][scol + 8] = na1;
                *(uint4*)&Bs[nb][srow][scol]     = nb0;
                *(uint4*)&Bs[nb][srow][scol + 8] = nb1;
                __syncthreads();
            }
        }
    }

    // epilogue: lane l holds c[r + {0,8}][c + {0,1}], r = l>>2, c = 2*(l&3)
    // (masked/dead rows have acc = 0 -> TANH path yields tanh(bias) naturally)
    const int r  = lane >> 2;
    const int cq = (lane & 3) * 2;
#pragma unroll
    for (int mi = 0; mi < 2; ++mi) {
#pragma unroll
        for (int nj = 0; nj < 8; ++nj) {
            const int m1 = m0 + wm * 32 + mi * 16 + r;
            const int n1 = n0 + wn * 64 + nj * 8 + cq;
            float bb0 = b1 ? __ldg(b1 + n1) : 0.f;
            float bb1 = b1 ? __ldg(b1 + n1 + 1) : 0.f;
            if (b2) { bb0 += __ldg(b2 + n1); bb1 += __ldg(b2 + n1 + 1); }
            float v0 = acc[mi][nj][0] + bb0;
            float v1 = acc[mi][nj][1] + bb1;
            float v2 = acc[mi][nj][2] + bb0;
            float v3 = acc[mi][nj][3] + bb1;
            if (TANH) { v0 = tanhf(v0); v1 = tanhf(v1); v2 = tanhf(v2); v3 = tanhf(v3); }
            *(float2*)(C + (size_t)m1 * N + n1)       = make_float2(v0, v1);
            *(float2*)(C + (size_t)(m1 + 8) * N + n1) = make_float2(v2, v3);
        }
    }
}

// ---------------- persistent LSTM layer kernel (512 threads, k-split warps) ----------------
// R10-validated layout (k-stride-1 lane ownership, scalar W LDG). Batch-quad
// truncation (4/2/1 nests). Single-counter ticket barrier (R10-proven) with a
// release-scoped arrive replacing the explicit __threadfence.
#define FMA_NEST(QN)                                                          \
    _Pragma("unroll 1")                                                       \
    for (int j = 0; j < 4; ++j) {                                             \
        const int kb = j * 128 + lane;                                        \
        _Pragma("unroll")                                                     \
        for (int kc = 0; kc < 4; ++kc) {                                      \
            const int kk = kb + kc * 32;                                      \
            const float w0 = __ldg(w0p + kk);                                 \
            const float w1 = __ldg(w1p + kk);                                 \
            const float w2 = __ldg(w2p + kk);                                 \
            const float w3 = __ldg(w3p + kk);                                 \
            const ull wp0 = pack2(w0, w0);                                    \
            const ull wp1 = pack2(w1, w1);                                    \
            const ull wp2 = pack2(w2, w2);                                    \
            const ull wp3 = pack2(w3, w3);                                    \
            const float* hrow = hs + (koff + kk) * HSTRIDE;                   \
            _Pragma("unroll")                                                 \
            for (int bq = 0; bq < (QN); ++bq) {                               \
                const ulonglong2 h2 = *(const ulonglong2*)(hrow + bq * 4);    \
                const int i0 = (2 * bq) * 4;                                  \
                const int i1 = (2 * bq + 1) * 4;                              \
                acc[i0+0] = fma2(wp0, h2.x, acc[i0+0]);                       \
                acc[i0+1] = fma2(wp1, h2.x, acc[i0+1]);                       \
                acc[i0+2] = fma2(wp2, h2.x, acc[i0+2]);                       \
                acc[i0+3] = fma2(wp3, h2.x, acc[i0+3]);                       \
                acc[i1+0] = fma2(wp0, h2.y, acc[i1+0]);                       \
                acc[i1+1] = fma2(wp1, h2.y, acc[i1+1]);                       \
                acc[i1+2] = fma2(wp2, h2.y, acc[i1+2]);                       \
                acc[i1+3] = fma2(wp3, h2.y, acc[i1+3]);                       \
            }                                                                 \
        }                                                                     \
    }

__global__ void __launch_bounds__(512) lstm_layer_kernel(
    const float* __restrict__ Whh,   // [4096,1024]
    const float* __restrict__ xg,    // [B*T,4096]
    float* __restrict__ ys,          // [B*T,1024]
    float* __restrict__ hT,          // [1024,16]
    const int* __restrict__ ilens)
{
    extern __shared__ float hs[];                    // [1024][HSTRIDE]
    ull* comb = (ull*)(hs + CD_ * HSTRIDE);          // [8*32] flat
    const int tid  = threadIdx.x;
    const int lane = tid & 31;
    const int warp = tid >> 5;                       // 0..15
    const int wc   = warp & 7;
    const int kh   = warp >> 3;
    const int cell = blockIdx.x * 8 + wc;
    const ull  G   = (ull)gridDim.x;

    const int koff = kh * 512;
    const float* w0p = Whh + (size_t)(0 * CD_ + cell) * CD_ + koff;
    const float* w1p = Whh + (size_t)(1 * CD_ + cell) * CD_ + koff;
    const float* w2p = Whh + (size_t)(2 * CD_ + cell) * CD_ + koff;
    const float* w3p = Whh + (size_t)(3 * CD_ + cell) * CD_ + koff;

    const int il_reg = (lane < B_) ? __ldg(ilens + lane) : 0;
    float creg = 0.f;

    for (int t = 0; t < T_; ++t) {
        const uint bal  = __ballot_sync(0xffffffffu, t < il_reg);
        const int  live = __popc(bal);               // live batches (>=1)
        const bool alive = (kh == 0) && (lane < B_) && (t < il_reg);

        float xgi = 0.f, xgf = 0.f, xgg = 0.f, xgo = 0.f;
        size_t orow = 0;
        if (alive) {
            orow = (size_t)(lane * T_ + t);
            const float* xr = xg + orow * GD_ + cell;
            xgi = __ldg(xr);
            xgf = __ldg(xr + CD_);
            xgg = __ldg(xr + 2 * CD_);
            xgo = __ldg(xr + 3 * CD_);
        }

        ull acc[32];
#pragma unroll
        for (int i = 0; i < 32; ++i) acc[i] = 0ULL;

        if (t > 0) {
            const int qn = (live > 8) ? 4 : ((live > 4) ? 2 : 1);  // staged quads
            const float4* src = (const float4*)hT;
#pragma unroll 4
            for (int i = tid; i < CD_ * B_ / 4; i += 512) {
                if ((i & 3) < qn) {
                    float4 v = __ldcg(src + i);
                    const int k  = i >> 2;
                    const int bq = (i & 3) * 4;
                    *(float4*)(hs + k * HSTRIDE + bq) = v;   // one STS.128
                }
            }
            __syncthreads();

            if (live > 8)      { FMA_NEST(4) }
            else if (live > 4) { FMA_NEST(2) }
            else               { FMA_NEST(1) }
        }

#pragma unroll
        for (int s = 0; s < 5; ++s) {
            const int off = 16 >> s;
            const int n   = 16 >> s;
            const bool hi = (lane & off) != 0;
#pragma unroll
            for (int i = 0; i < n; ++i) {
                ull send = hi ? acc[i] : acc[i + n];
                ull r = __shfl_xor_sync(0xffffffffu, send, off);
                acc[i] = add2(hi ? acc[i + n] : acc[i], r);
            }
        }

        if (kh == 1) comb[wc * 32 + lane] = acc[0];
        __syncthreads();
        ull tot = acc[0];
        if (kh == 0) tot = add2(tot, comb[wc * 32 + lane]);

        const int srcl = (lane >> 1) * 4;
        const ull r0 = __shfl_sync(0xffffffffu, tot, srcl + 0);
        const ull r1 = __shfl_sync(0xffffffffu, tot, srcl + 1);
        const ull r2 = __shfl_sync(0xffffffffu, tot, srcl + 2);
        const ull r3 = __shfl_sync(0xffffffffu, tot, srcl + 3);

        if (alive) {
            const bool oddb = (lane & 1) != 0;
            const float2 p0 = unpack2(r0), p1 = unpack2(r1), p2 = unpack2(r2), p3 = unpack2(r3);
            const float gi = (oddb ? p0.y : p0.x) + xgi;
            const float gf = (oddb ? p1.y : p1.x) + xgf;
            const float gg = (oddb ? p2.y : p2.x) + xgg;
            const float go = (oddb ? p3.y : p3.x) + xgo;
            const float cn = sigf(gf) * creg + sigf(gi) * tanhf(gg);
            creg = cn;
            const float hn = sigf(go) * tanhf(cn);
            hT[cell * B_ + lane]  = hn;     // cross-block critical path first
            ys[orow * CD_ + cell] = hn;
        }

        // ---- grid-wide ticket barrier (monotonic, replay-safe) ----
        // bar.sync orders all warps' h writes before tid0's RELEASE arrive.
        __syncthreads();
        if (tid == 0) {
            ull x = arrive_release(&g_bar);
            ull target = x - (x % G) + G;
            while (*(volatile ull*)&g_bar < target) { }
        }
        __syncthreads();
    }
}

// ---------------- ilens tail ----------------
__global__ void write_tail_kernel(float* __restrict__ out, const int* __restrict__ ilens,
                                  long long base, long long out_size) {
    int i = threadIdx.x;
    if (i < B_ && base + i < out_size) out[base + i] = (float)ilens[i];
}

// ---------------- launch ----------------
extern "C" void kernel_launch(void* const* d_in, const int* in_sizes, int n_in,
                              void* d_out, int out_size)
{
    const float* xpad  = (const float*)d_in[0];   // [B,T,IDIM]
    const float* Wih0  = (const float*)d_in[1];   // [4096,320]
    const float* WihR  = (const float*)d_in[2];   // [3,4096,1024]
    const float* Whh   = (const float*)d_in[3];   // [4,4096,1024]
    const float* bih   = (const float*)d_in[4];   // [4,4096]
    const float* bhh   = (const float*)d_in[5];   // [4,4096]
    const float* Wlast = (const float*)d_in[6];   // [1024,1024]
    const float* blast = (const float*)d_in[7];   // [1024]
    const int*   ilens = (const int*)d_in[8];     // [16]
    float* out = (float*)d_out;

    float *xg, *xb, *hT;
    __nv_bfloat16 *ah, *al, *bh, *bl;
    cudaGetSymbolAddress((void**)&xg, g_xg);
    cudaGetSymbolAddress((void**)&xb, g_x);
    cudaGetSymbolAddress((void**)&hT, g_hT);
    cudaGetSymbolAddress((void**)&ah, g_ah);
    cudaGetSymbolAddress((void**)&al, g_al);
    cudaGetSymbolAddress((void**)&bh, g_bh);
    cudaGetSymbolAddress((void**)&bl, g_bl);

    const int smem_step = CD_ * HSTRIDE * 4 + 8 * 32 * 8;  // 81920 + 2048
    cudaFuncSetAttribute(lstm_layer_kernel,
                         cudaFuncAttributeMaxDynamicSharedMemorySize, smem_step);

    const int M = B_ * T_;  // 8192

    for (int l = 0; l < LAYERS_; ++l) {
        const float* Ain = (l == 0) ? xpad : xb;
        const float* Bw  = (l == 0) ? Wih0 : (WihR + (size_t)(l - 1) * GD_ * CD_);
        const int K = (l == 0) ? IDIM_ : CD_;

        {
            int nA = M * K;
            conv_split_kernel<<<(nA / 2 + 255) / 256, 256>>>(Ain, ah, al, nA, K, nullptr);
            int nB = GD_ * K;
            conv_split_kernel<<<(nB / 2 + 255) / 256, 256>>>(Bw, bh, bl, nB, K, nullptr);
        }

        dim3 grid_xg(GD_ / 128, M / 128);
        gemm_bf16x3_kernel<0><<<grid_xg, 256>>>(ah, al, bh, bl,
                                                bih + l * GD_, bhh + l * GD_,
                                                xg, M, GD_, K, ilens);

        const float* Wl = Whh + (size_t)l * GD_ * CD_;
        lstm_layer_kernel<<<NBLK_, 512, smem_step>>>(Wl, xg, xb, hT, ilens);
    }

    // projection: conv masks dead rows (acc=0 -> tanh(bias)); dead tiles skip mainloop
    {
        int nA = M * CD_;
        conv_split_kernel<<<(nA / 2 + 255) / 256, 256>>>(xb, ah, al, nA, CD_, ilens);
        int nB = HD_ * CD_;
        conv_split_kernel<<<(nB / 2 + 255) / 256, 256>>>(Wlast, bh, bl, nB, CD_, nullptr);
        dim3 grid_p(HD_ / 128, M / 128);
        gemm_bf16x3_kernel<1><<<grid_p, 256>>>(ah, al, bh, bl, blast, nullptr,
                                               out, M, HD_, CD_, ilens);
    }

    const long long base = (long long)B_ * T_ * HD_;  // 8388608
    if ((long long)out_size > base)
        write_tail_kernel<<<1, 32>>>(out, ilens, base, (long long)out_size);
}

// round 17
// speedup vs baseline: 1.5303x; 1.0302x over previous
#include <cuda_runtime.h>
#include <cuda_bf16.h>
#include <math.h>
#include <cstdint>

#define B_ 16
#define T_ 512
#define IDIM_ 320
#define CD_ 1024
#define GD_ 4096   // 4*CD
#define HD_ 1024
#define LAYERS_ 4
#define NBLK_ 128  // persistent grid: <= 148 SMs -> all co-resident

typedef unsigned long long ull;
typedef unsigned int uint;

// ---------------- scratch (static device globals; no runtime alloc) ----------------
__device__ float g_xg[(size_t)B_ * T_ * GD_];        // precomputed input gates
__device__ float g_x [(size_t)B_ * T_ * CD_];        // layer io buffer (ys)
__device__ float g_hT[CD_ * B_];                     // h transposed: hT[cell][b]
__device__ ull   g_bar;                              // ticket barrier (monotonic)
__device__ __align__(16) __nv_bfloat16 g_ah[(size_t)B_ * T_ * CD_]; // A hi
__device__ __align__(16) __nv_bfloat16 g_al[(size_t)B_ * T_ * CD_]; // A lo
__device__ __align__(16) __nv_bfloat16 g_bh[(size_t)GD_ * CD_];     // B hi
__device__ __align__(16) __nv_bfloat16 g_bl[(size_t)GD_ * CD_];     // B lo

// ---------------- packed fp32x2 helpers (step kernel) ----------------
__device__ __forceinline__ ull fma2(ull a, ull b, ull c) {
    ull d;
    asm("fma.rn.f32x2 %0, %1, %2, %3;" : "=l"(d) : "l"(a), "l"(b), "l"(c));
    return d;
}
__device__ __forceinline__ ull add2(ull a, ull b) {
    ull d;
    asm("add.rn.f32x2 %0, %1, %2;" : "=l"(d) : "l"(a), "l"(b));
    return d;
}
__device__ __forceinline__ ull pack2(float x, float y) {
    ull d;
    asm("mov.b64 %0, {%1, %2};" : "=l"(d) : "f"(x), "f"(y));
    return d;
}
__device__ __forceinline__ float2 unpack2(ull v) {
    float2 r;
    asm("mov.b64 {%0, %1}, %2;" : "=f"(r.x), "=f"(r.y) : "l"(v));
    return r;
}
__device__ __forceinline__ float sigf(float x) { return 1.f / (1.f + expf(-x)); }

// release-scoped ticket arrive: orders all prior (bar-ordered) writes at gpu scope
__device__ __forceinline__ ull arrive_release(ull* ctr) {
    ull x;
    asm volatile("atom.release.gpu.global.add.u64 %0, [%1], %2;"
                 : "=l"(x) : "l"(ctr), "l"(1ULL) : "memory");
    return x;
}

#define HSTRIDE 20   // padded row stride (floats) for transposed h in smem

// ---------------- bf16 split conversion ----------------
__global__ void __launch_bounds__(256) conv_split_kernel(
    const float* __restrict__ x, __nv_bfloat16* __restrict__ hi,
    __nv_bfloat16* __restrict__ lo, int n, int K, const int* __restrict__ ilens)
{
    int i = (blockIdx.x * 256 + threadIdx.x) * 2;
    if (i >= n) return;
    float2 v = *(const float2*)(x + i);
    if (ilens) {
        int m = i / K;
        int t = m & (T_ - 1);
        int b = m >> 9;
        if (t >= ilens[b]) { v.x = 0.f; v.y = 0.f; }
    }
    __nv_bfloat162 h2, l2;
    h2.x = __float2bfloat16_rn(v.x);
    h2.y = __float2bfloat16_rn(v.y);
    l2.x = __float2bfloat16_rn(v.x - __bfloat162float(h2.x));
    l2.y = __float2bfloat16_rn(v.y - __bfloat162float(h2.y));
    *(__nv_bfloat162*)(hi + i) = h2;
    *(__nv_bfloat162*)(lo + i) = l2;
}

// ---------------- MMA helpers ----------------
__device__ __forceinline__ void ldmx4(uint& r0, uint& r1, uint& r2, uint& r3,
                                      const __nv_bfloat16* p) {
    uint a = (uint)__cvta_generic_to_shared(p);
    asm volatile("ldmatrix.sync.aligned.m8n8.x4.shared.b16 {%0,%1,%2,%3}, [%4];"
                 : "=r"(r0), "=r"(r1), "=r"(r2), "=r"(r3) : "r"(a));
}
__device__ __forceinline__ void mma16816(float* d, const uint* a, uint b0, uint b1) {
    asm volatile(
        "mma.sync.aligned.m16n8k16.row.col.f32.bf16.bf16.f32 "
        "{%0,%1,%2,%3}, {%4,%5,%6,%7}, {%8,%9}, {%0,%1,%2,%3};"
        : "+f"(d[0]), "+f"(d[1]), "+f"(d[2]), "+f"(d[3])
        : "r"(a[0]), "r"(a[1]), "r"(a[2]), "r"(a[3]), "r"(b0), "r"(b1));
}

// ---------------- bf16x3 GEMM (NT): C = A*B^T + bias, fp32 accum ----------------
// R5-validated structure: 128x128x32 tiles, 256 threads, 8 warps (4M x 2N,
// warp 32x64), register-prefetch ping-pong smem, ONE sync per slab.
// Virtual K'' = 3K over segments (Ah,Bh),(Al,Bh),(Ah,Bl).
// Dead tiles (t0 >= ilens[b]): TANH=0 return; TANH=1 skip mainloop -> tanh(bias).
#define SPAD 40  // bf16 row stride (32 + 8 pad): conflict-free ldmatrix phases
template <int TANH>
__global__ void __launch_bounds__(256) gemm_bf16x3_kernel(
    const __nv_bfloat16* __restrict__ Ah, const __nv_bfloat16* __restrict__ Al,
    const __nv_bfloat16* __restrict__ Bh, const __nv_bfloat16* __restrict__ Bl,
    const float* __restrict__ b1, const float* __restrict__ b2,
    float* __restrict__ C, int M, int N, int K, const int* __restrict__ ilens)
{
    __shared__ __align__(16) __nv_bfloat16 As[2][128][SPAD];
    __shared__ __align__(16) __nv_bfloat16 Bs[2][128][SPAD];

    const int tid  = threadIdx.x;
    const int m0   = blockIdx.y * 128;
    const int n0   = blockIdx.x * 128;
    const int srow = tid >> 1;
    const int scol = (tid & 1) * 16;
    const int lane = tid & 31;
    const int warp = tid >> 5;
    const int wm   = warp & 3;
    const int wn   = warp >> 2;

    const bool tdead = ((m0 & 511) >= __ldg(ilens + (m0 >> 9)));
    if (!TANH && tdead) return;

    const int perseg = K >> 5;
    const int nslab  = 3 * perseg;

    float acc[2][8][4];
#pragma unroll
    for (int i = 0; i < 2; ++i)
#pragma unroll
        for (int j = 0; j < 8; ++j)
#pragma unroll
            for (int q = 0; q < 4; ++q) acc[i][j][q] = 0.f;

    if (!tdead) {
        auto srcA = [&](int s) -> const uint4* {
            int seg = s / perseg, kin = (s - seg * perseg) * 32;
            const __nv_bfloat16* A = (seg == 1) ? Al : Ah;
            return (const uint4*)(A + (size_t)(m0 + srow) * K + kin + scol);
        };
        auto srcB = [&](int s) -> const uint4* {
            int seg = s / perseg, kin = (s - seg * perseg) * 32;
            const __nv_bfloat16* Bp = (seg == 2) ? Bl : Bh;
            return (const uint4*)(Bp + (size_t)(n0 + srow) * K + kin + scol);
        };

        {
            const uint4* pa = srcA(0);
            const uint4* pb = srcB(0);
            uint4 a0 = pa[0], a1 = pa[1], bq0 = pb[0], bq1 = pb[1];
            *(uint4*)&As[0][srow][scol]     = a0;
            *(uint4*)&As[0][srow][scol + 8] = a1;
            *(uint4*)&Bs[0][srow][scol]     = bq0;
            *(uint4*)&Bs[0][srow][scol + 8] = bq1;
        }
        __syncthreads();

        for (int s = 0; s < nslab; ++s) {
            const int buf = s & 1;
            const bool has = (s + 1) < nslab;
            uint4 na0, na1, nb0, nb1;
            if (has) {
                const uint4* pa = srcA(s + 1);
                const uint4* pb = srcB(s + 1);
                na0 = pa[0]; na1 = pa[1]; nb0 = pb[0]; nb1 = pb[1];
            }

#pragma unroll
            for (int kh = 0; kh < 2; ++kh) {
                const int rq = lane & 15;
                const int cq = kh * 16 + ((lane >> 4) << 3);
                uint af[2][4];
#pragma unroll
                for (int mi = 0; mi < 2; ++mi)
                    ldmx4(af[mi][0], af[mi][1], af[mi][2], af[mi][3],
                          &As[buf][wm * 32 + mi * 16 + rq][cq]);
                uint bf4[4][4];
#pragma unroll
                for (int nq = 0; nq < 4; ++nq)
                    ldmx4(bf4[nq][0], bf4[nq][1], bf4[nq][2], bf4[nq][3],
                          &Bs[buf][wn * 64 + nq * 16 + rq][cq]);
#pragma unroll
                for (int mi = 0; mi < 2; ++mi)
#pragma unroll
                    for (int nq = 0; nq < 4; ++nq) {
                        mma16816(acc[mi][2 * nq],     af[mi], bf4[nq][0], bf4[nq][2]);
                        mma16816(acc[mi][2 * nq + 1], af[mi], bf4[nq][1], bf4[nq][3]);
                    }
            }

            if (has) {
                const int nb = buf ^ 1;
                *(uint4*)&As[nb][srow][scol]     = na0;
                *(uint4*)&As[nb][srow][scol + 8] = na1;
                *(uint4*)&Bs[nb][srow][scol]     = nb0;
                *(uint4*)&Bs[nb][srow][scol + 8] = nb1;
                __syncthreads();
            }
        }
    }

    const int r  = lane >> 2;
    const int cq = (lane & 3) * 2;
#pragma unroll
    for (int mi = 0; mi < 2; ++mi) {
#pragma unroll
        for (int nj = 0; nj < 8; ++nj) {
            const int m1 = m0 + wm * 32 + mi * 16 + r;
            const int n1 = n0 + wn * 64 + nj * 8 + cq;
            float bb0 = b1 ? __ldg(b1 + n1) : 0.f;
            float bb1 = b1 ? __ldg(b1 + n1 + 1) : 0.f;
            if (b2) { bb0 += __ldg(b2 + n1); bb1 += __ldg(b2 + n1 + 1); }
            float v0 = acc[mi][nj][0] + bb0;
            float v1 = acc[mi][nj][1] + bb1;
            float v2 = acc[mi][nj][2] + bb0;
            float v3 = acc[mi][nj][3] + bb1;
            if (TANH) { v0 = tanhf(v0); v1 = tanhf(v1); v2 = tanhf(v2); v3 = tanhf(v3); }
            *(float2*)(C + (size_t)m1 * N + n1)       = make_float2(v0, v1);
            *(float2*)(C + (size_t)(m1 + 8) * N + n1) = make_float2(v2, v3);
        }
    }
}

// ---------------- persistent LSTM layer kernel (512 threads) ----------------
// Warp tile re-shaped to (2 cells x 8 batches x k-half): halves h smem reads
// (reuse 8 per h2 vs 4). 16 warps: cp = warp&3 (cell pair), bh = (warp>>2)&1
// (batch half), kh = warp>>3 (k half). acc[c*16 + bp*4 + g] (32 ull, same
// count as before; butterfly/comb identical). Truncation via sorted ilens:
// bh=1 warps skip nest when live<=8; bh=0 warps run half-nest when live<=4.
// HB = number of batch quads this warp processes (2 = 8 batches, 1 = 4).
#define NEST2(HB)                                                             \
    _Pragma("unroll 1")                                                       \
    for (int j = 0; j < 4; ++j) {                                             \
        _Pragma("unroll")                                                     \
        for (int kc = 0; kc < 4; ++kc) {                                      \
            const int k = koff + j * 128 + lane + kc * 32;                    \
            const float* hrow = hs + k * HSTRIDE + bh * 8;                    \
            const ulonglong2 ha = *(const ulonglong2*)hrow;                   \
            ulonglong2 hbq = ha;                                              \
            if (HB > 1) hbq = *(const ulonglong2*)(hrow + 4);                 \
            _Pragma("unroll")                                                 \
            for (int g = 0; g < 4; ++g) {                                     \
                const float wa = __ldg(wgp[g] + k);                           \
                const float wb = __ldg(wgp[g] + k + CD_);                     \
                const ull wpa = pack2(wa, wa);                                \
                const ull wpb = pack2(wb, wb);                                \
                acc[ 0 + g] = fma2(wpa, ha.x,  acc[ 0 + g]);                  \
                acc[ 4 + g] = fma2(wpa, ha.y,  acc[ 4 + g]);                  \
                acc[16 + g] = fma2(wpb, ha.x,  acc[16 + g]);                  \
                acc[20 + g] = fma2(wpb, ha.y,  acc[20 + g]);                  \
                if (HB > 1) {                                                 \
                    acc[ 8 + g] = fma2(wpa, hbq.x, acc[ 8 + g]);              \
                    acc[12 + g] = fma2(wpa, hbq.y, acc[12 + g]);              \
                    acc[24 + g] = fma2(wpb, hbq.x, acc[24 + g]);              \
                    acc[28 + g] = fma2(wpb, hbq.y, acc[28 + g]);              \
                }                                                             \
            }                                                                 \
        }                                                                     \
    }

__global__ void __launch_bounds__(512) lstm_layer_kernel(
    const float* __restrict__ Whh,   // [4096,1024]
    const float* __restrict__ xg,    // [B*T,4096]
    float* __restrict__ ys,          // [B*T,1024]
    float* __restrict__ hT,          // [1024,16]
    const int* __restrict__ ilens)
{
    extern __shared__ float hs[];                    // [1024][HSTRIDE]
    ull* comb = (ull*)(hs + CD_ * HSTRIDE);          // [8*32] flat
    const int tid  = threadIdx.x;
    const int lane = tid & 31;
    const int warp = tid >> 5;                       // 0..15
    const int cp   = warp & 3;                       // cell pair 0..3
    const int bh   = (warp >> 2) & 1;                // batch half
    const int kh   = warp >> 3;                      // k half
    const int cell0 = blockIdx.x * 8 + cp * 2;       // first cell of pair
    const ull  G   = (ull)gridDim.x;

    const int koff = kh * 512;
    // gate-row base pointers for cell0 (cell0+1 = +CD_ immediate in NEST2)
    const float* wgp[4];
#pragma unroll
    for (int g = 0; g < 4; ++g)
        wgp[g] = Whh + (size_t)(g * CD_ + cell0) * CD_;

    const int bloc = lane & 7;
    const int bown = bh * 8 + bloc;                  // this lane's batch (lane<16)
    const int il_glob = (lane < B_) ? __ldg(ilens + lane) : 0;   // ballot source
    const int il_own  = (lane < 16) ? __ldg(ilens + bown) : 0;   // update gate
    const int c_loc   = (lane >> 3) & 1;             // local cell for update
    float creg = 0.f;

    for (int t = 0; t < T_; ++t) {
        const uint bal  = __ballot_sync(0xffffffffu, t < il_glob);
        const int  live = __popc(bal);               // live batches (>=1, sorted desc)
        const bool alive = (kh == 0) && (lane < 16) && (t < il_own);

        float xgi = 0.f, xgf = 0.f, xgg = 0.f, xgo = 0.f;
        size_t orow = 0;
        int cell_u = 0;
        if (alive) {
            cell_u = cell0 + c_loc;
            orow = (size_t)(bown * T_ + t);
            const float* xr = xg + orow * GD_ + cell_u;
            xgi = __ldg(xr);
            xgf = __ldg(xr + CD_);
            xgg = __ldg(xr + 2 * CD_);
            xgo = __ldg(xr + 3 * CD_);
        }

        ull acc[32];
#pragma unroll
        for (int i = 0; i < 32; ++i) acc[i] = 0ULL;

        if (t > 0) {
            const int qn = (live > 8) ? 4 : ((live > 4) ? 2 : 1);  // staged quads
            const float4* src = (const float4*)hT;
#pragma unroll 4
            for (int i = tid; i < CD_ * B_ / 4; i += 512) {
                if ((i & 3) < qn) {
                    float4 v = __ldcg(src + i);
                    const int k  = i >> 2;
                    const int bq = (i & 3) * 4;
                    *(float4*)(hs + k * HSTRIDE + bq) = v;
                }
            }
            __syncthreads();

            if (bh == 0) {
                if (live > 4) { NEST2(2) } else { NEST2(1) }
            } else {
                if (live > 8) { NEST2(2) }
            }
        }

        // butterfly on 32 packed values: lane l ends holding full packed sum of idx l
#pragma unroll
        for (int s = 0; s < 5; ++s) {
            const int off = 16 >> s;
            const int n   = 16 >> s;
            const bool hi = (lane & off) != 0;
#pragma unroll
            for (int i = 0; i < n; ++i) {
                ull send = hi ? acc[i] : acc[i + n];
                ull r = __shfl_xor_sync(0xffffffffu, send, off);
                acc[i] = add2(hi ? acc[i + n] : acc[i], r);
            }
        }

        // combine the two k-halves via smem (partner warp = same cp,bh)
        if (kh == 1) comb[(warp & 7) * 32 + lane] = acc[0];
        __syncthreads();
        ull tot = acc[0];
        if (kh == 0) tot = add2(tot, comb[warp * 32 + lane]);

        // gather gates of (c_loc, bown): value idx = c_loc*16 + (bloc>>1)*4 + g
        const int srcl = c_loc * 16 + (bloc >> 1) * 4;
        const ull r0 = __shfl_sync(0xffffffffu, tot, srcl + 0);
        const ull r1 = __shfl_sync(0xffffffffu, tot, srcl + 1);
        const ull r2 = __shfl_sync(0xffffffffu, tot, srcl + 2);
        const ull r3 = __shfl_sync(0xffffffffu, tot, srcl + 3);

        if (alive) {
            const bool oddb = (bloc & 1) != 0;
            const float2 p0 = unpack2(r0), p1 = unpack2(r1), p2 = unpack2(r2), p3 = unpack2(r3);
            const float gi = (oddb ? p0.y : p0.x) + xgi;
            const float gf = (oddb ? p1.y : p1.x) + xgf;
            const float gg = (oddb ? p2.y : p2.x) + xgg;
            const float go = (oddb ? p3.y : p3.x) + xgo;
            const float cn = sigf(gf) * creg + sigf(gi) * tanhf(gg);
            creg = cn;
            const float hn = sigf(go) * tanhf(cn);
            hT[cell_u * B_ + bown] = hn;    // cross-block critical path first
            ys[orow * CD_ + cell_u] = hn;
        }

        // ---- grid-wide ticket barrier (monotonic, replay-safe) ----
        __syncthreads();
        if (tid == 0) {
            ull x = arrive_release(&g_bar);
            ull target = x - (x % G) + G;
            while (*(volatile ull*)&g_bar < target) { }
        }
        __syncthreads();
    }
}

// ---------------- ilens tail ----------------
__global__ void write_tail_kernel(float* __restrict__ out, const int* __restrict__ ilens,
                                  long long base, long long out_size) {
    int i = threadIdx.x;
    if (i < B_ && base + i < out_size) out[base + i] = (float)ilens[i];
}

// ---------------- launch ----------------
extern "C" void kernel_launch(void* const* d_in, const int* in_sizes, int n_in,
                              void* d_out, int out_size)
{
    const float* xpad  = (const float*)d_in[0];   // [B,T,IDIM]
    const float* Wih0  = (const float*)d_in[1];   // [4096,320]
    const float* WihR  = (const float*)d_in[2];   // [3,4096,1024]
    const float* Whh   = (const float*)d_in[3];   // [4,4096,1024]
    const float* bih   = (const float*)d_in[4];   // [4,4096]
    const float* bhh   = (const float*)d_in[5];   // [4,4096]
    const float* Wlast = (const float*)d_in[6];   // [1024,1024]
    const float* blast = (const float*)d_in[7];   // [1024]
    const int*   ilens = (const int*)d_in[8];     // [16]
    float* out = (float*)d_out;

    float *xg, *xb, *hT;
    __nv_bfloat16 *ah, *al, *bh, *bl;
    cudaGetSymbolAddress((void**)&xg, g_xg);
    cudaGetSymbolAddress((void**)&xb, g_x);
    cudaGetSymbolAddress((void**)&hT, g_hT);
    cudaGetSymbolAddress((void**)&ah, g_ah);
    cudaGetSymbolAddress((void**)&al, g_al);
    cudaGetSymbolAddress((void**)&bh, g_bh);
    cudaGetSymbolAddress((void**)&bl, g_bl);

    const int smem_step = CD_ * HSTRIDE * 4 + 8 * 32 * 8;  // 81920 + 2048
    cudaFuncSetAttribute(lstm_layer_kernel,
                         cudaFuncAttributeMaxDynamicSharedMemorySize, smem_step);

    const int M = B_ * T_;  // 8192

    for (int l = 0; l < LAYERS_; ++l) {
        const float* Ain = (l == 0) ? xpad : xb;
        const float* Bw  = (l == 0) ? Wih0 : (WihR + (size_t)(l - 1) * GD_ * CD_);
        const int K = (l == 0) ? IDIM_ : CD_;

        {
            int nA = M * K;
            conv_split_kernel<<<(nA / 2 + 255) / 256, 256>>>(Ain, ah, al, nA, K, nullptr);
            int nB = GD_ * K;
            conv_split_kernel<<<(nB / 2 + 255) / 256, 256>>>(Bw, bh, bl, nB, K, nullptr);
        }

        dim3 grid_xg(GD_ / 128, M / 128);
        gemm_bf16x3_kernel<0><<<grid_xg, 256>>>(ah, al, bh, bl,
                                                bih + l * GD_, bhh + l * GD_,
                                                xg, M, GD_, K, ilens);

        const float* Wl = Whh + (size_t)l * GD_ * CD_;
        lstm_layer_kernel<<<NBLK_, 512, smem_step>>>(Wl, xg, xb, hT, ilens);
    }

    // projection: conv masks dead rows (acc=0 -> tanh(bias)); dead tiles skip mainloop
    {
        int nA = M * CD_;
        conv_split_kernel<<<(nA / 2 + 255) / 256, 256>>>(xb, ah, al, nA, CD_, ilens);
        int nB = HD_ * CD_;
        conv_split_kernel<<<(nB / 2 + 255) / 256, 256>>>(Wlast, bh, bl, nB, CD_, nullptr);
        dim3 grid_p(HD_ / 128, M / 128);
        gemm_bf16x3_kernel<1><<<grid_p, 256>>>(ah, al, bh, bl, blast, nullptr,
                                               out, M, HD_, CD_, ilens);
    }

    const long long base = (long long)B_ * T_ * HD_;  // 8388608
    if ((long long)out_size > base)
        write_tail_kernel<<<1, 32>>>(out, ilens, base, (long long)out_size);
}